// round 11
// baseline (speedup 1.0000x reference)
#include <cuda_runtime.h>
#include <cstdint>
#include <math.h>

// Problem constants
#define B_  2
#define T_  2048
#define C_  1024
#define H_  16
#define D_  64
#define BT_ (B_*T_)          // 4096
#define C3_ (3*C_)           // 3072

// Scratch (device globals: allocation-guard safe)
__device__ float g_qkv[BT_ * C3_];   // (B*T, 3C), stored tf32-rounded
__device__ float g_y[BT_ * C_];      // (B*T, C), stored tf32-rounded
__device__ float g_xr[BT_ * C_];     // x, tf32-rounded
__device__ float g_WT1[C3_ * C_];    // W_attn^T, tf32-rounded
__device__ float g_WT2[C_ * C_];     // W_proj^T, tf32-rounded

__device__ __forceinline__ float to_tf32(float f) {
    uint32_t u;
    asm("cvt.rna.tf32.f32 %0, %1;" : "=r"(u) : "f"(f));
    return __uint_as_float(u);
}

__device__ __forceinline__ void mma_tf32(float* d, const uint32_t* a, const uint32_t* b) {
    asm volatile(
        "mma.sync.aligned.m16n8k8.row.col.f32.tf32.tf32.f32 "
        "{%0,%1,%2,%3}, {%4,%5,%6,%7}, {%8,%9}, {%0,%1,%2,%3};"
        : "+f"(d[0]), "+f"(d[1]), "+f"(d[2]), "+f"(d[3])
        : "r"(a[0]), "r"(a[1]), "r"(a[2]), "r"(a[3]), "r"(b[0]), "r"(b[1]));
}

__device__ __forceinline__ uint32_t smem_u32(const void* p) {
    uint32_t a;
    asm("{ .reg .u64 t; cvta.to.shared.u64 t, %1; cvt.u32.u64 %0, t; }" : "=r"(a) : "l"(p));
    return a;
}
__device__ __forceinline__ void cp_async16(uint32_t saddr, const void* g) {
    asm volatile("cp.async.cg.shared.global [%0], [%1], 16;" :: "r"(saddr), "l"(g));
}
#define CP_COMMIT()  asm volatile("cp.async.commit_group;" ::: "memory")
#define CP_WAIT(n)   asm volatile("cp.async.wait_group %0;" :: "n"(n) : "memory")

// ============================================================================
// Elementwise tf32 rounding (vectorized): out[i] = tf32(in[i])
// ============================================================================
__global__ void round_tf32_kernel(const float* __restrict__ in, float* __restrict__ out)
{
    const int i = (blockIdx.x * blockDim.x + threadIdx.x) * 4;
    float4 v = *(const float4*)&in[i];
    v.x = to_tf32(v.x); v.y = to_tf32(v.y);
    v.z = to_tf32(v.z); v.w = to_tf32(v.w);
    *(float4*)&out[i] = v;
}

// ============================================================================
// Transpose + tf32-round: out[n][k] = tf32(in[k][n]).
// ============================================================================
__global__ void transpose_tf32_kernel(const float* __restrict__ in, float* __restrict__ out,
                                      int R, int Cc)
{
    __shared__ float tile[32][33];
    const int bx = blockIdx.x * 32;
    const int by = blockIdx.y * 32;
    #pragma unroll
    for (int j = 0; j < 32; j += 8)
        tile[threadIdx.y + j][threadIdx.x] = in[(size_t)(by + threadIdx.y + j) * Cc + bx + threadIdx.x];
    __syncthreads();
    #pragma unroll
    for (int j = 0; j < 32; j += 8)
        out[(size_t)(bx + threadIdx.y + j) * R + by + threadIdx.x] =
            to_tf32(tile[threadIdx.x][threadIdx.y + j]);
}

// ============================================================================
// tf32 mma.sync GEMM:  Cmat[M,N] = A[M,K] @ BT[N,K]^T + bias[N]
// Operands pre-rounded to tf32. cp.async double-buffered, BK=32;
// prefetch issued at chunk top, wait_group 0 + barrier at chunk bottom.
// CTA tile 256x128, 256 threads = 8 warps as 4(m) x 2(n), warp tile 64x64.
// Smem (floats): A stage s at s*8224, slice kq at +kq*1028 (16B pad per slice
// -> conflict-free cp.async stores); B base 16448, stage stride 4128,
// slice stride 516. Fragment reads conflict-free as before.
// ============================================================================
#define A_SLICE  1028
#define A_STAGE  8224
#define B_BASE   16448
#define B_SLICE  516
#define B_STAGE  4128
#define GEMM_SMEM_BYTES ((2 * A_STAGE + 2 * B_STAGE) * 4)   // 98816 B

__global__ __launch_bounds__(256, 1) void gemm_mma_kernel(
    const float* __restrict__ A, const float* __restrict__ BT,
    const float* __restrict__ bias, float* __restrict__ Cmat,
    int M, int N, int K, int roundOut)
{
    extern __shared__ __align__(16) float sm[];

    const int tid  = threadIdx.x;
    const int lane = tid & 31;
    const int warp = tid >> 5;
    const int wr = warp >> 1;            // 0..3 -> m offset wr*64
    const int wc = warp & 1;             // 0..1 -> n offset wc*64
    const int g  = lane >> 2;            // 0..7
    const int kc = lane & 3;             // 0..3

    const int m0 = blockIdx.y * 256;
    const int n0 = blockIdx.x * 128;

    const int lm  = tid >> 3;            // 0..31 (load row group)
    const int lkq = tid & 7;             // 0..7  (load k-quad)

    const uint32_t smb = smem_u32(sm);

    float acc[4][8][4];
    #pragma unroll
    for (int mf = 0; mf < 4; mf++)
        #pragma unroll
        for (int nf = 0; nf < 8; nf++)
            #pragma unroll
            for (int r = 0; r < 4; r++) acc[mf][nf][r] = 0.f;

    const int nch = K >> 5;              // K/32

    // chunk issuer: 8 A-cells + 4 B-cells per thread, fully coalesced
    auto issue_chunk = [&](int stage, int k0) {
        #pragma unroll
        for (int it = 0; it < 8; it++) {
            const int row = lm + it * 32;
            cp_async16(smb + (uint32_t)((stage * A_STAGE + lkq * A_SLICE + row * 4) * 4),
                       &A[(size_t)(m0 + row) * K + k0 + 4 * lkq]);
        }
        #pragma unroll
        for (int it = 0; it < 4; it++) {
            const int row = lm + it * 32;
            cp_async16(smb + (uint32_t)((B_BASE + stage * B_STAGE + lkq * B_SLICE + row * 4) * 4),
                       &BT[(size_t)(n0 + row) * K + k0 + 4 * lkq]);
        }
        CP_COMMIT();
    };

    // prologue: chunk 0 -> stage 0
    issue_chunk(0, 0);
    CP_WAIT(0);
    __syncthreads();

    for (int ic = 0; ic < nch; ic++) {
        const int cur = ic & 1;
        const bool more = (ic + 1) < nch;
        if (more) issue_chunk(cur ^ 1, (ic + 1) << 5);   // prefetch while computing

        const float* As = &sm[cur * A_STAGE];
        const float* Bs = &sm[B_BASE + cur * B_STAGE];

        #pragma unroll
        for (int t = 0; t < 4; t++) {
            uint32_t bf[8][2];
            #pragma unroll
            for (int nf = 0; nf < 8; nf++) {
                const int n = wc * 64 + nf * 8 + g;
                bf[nf][0] = __float_as_uint(Bs[(2 * t + 0) * B_SLICE + n * 4 + kc]);
                bf[nf][1] = __float_as_uint(Bs[(2 * t + 1) * B_SLICE + n * 4 + kc]);
            }
            #pragma unroll
            for (int mf = 0; mf < 4; mf++) {
                const int m = wr * 64 + mf * 16 + g;
                uint32_t af[4];
                af[0] = __float_as_uint(As[(2 * t + 0) * A_SLICE + m * 4 + kc]);
                af[1] = __float_as_uint(As[(2 * t + 0) * A_SLICE + (m + 8) * 4 + kc]);
                af[2] = __float_as_uint(As[(2 * t + 1) * A_SLICE + m * 4 + kc]);
                af[3] = __float_as_uint(As[(2 * t + 1) * A_SLICE + (m + 8) * 4 + kc]);
                #pragma unroll
                for (int nf = 0; nf < 8; nf++)
                    mma_tf32(acc[mf][nf], af, bf[nf]);
            }
        }

        if (more) CP_WAIT(0);   // prefetch had the whole compute phase to land
        __syncthreads();
    }

    // ---- epilogue: acc -> gmem with bias
    #pragma unroll
    for (int mf = 0; mf < 4; mf++) {
        const int row = m0 + wr * 64 + mf * 16 + g;
        #pragma unroll
        for (int nf = 0; nf < 8; nf++) {
            const int col = n0 + wc * 64 + nf * 8 + kc * 2;
            const float b0 = bias[col];
            const float b1 = bias[col + 1];
            float2 o0 = { acc[mf][nf][0] + b0, acc[mf][nf][1] + b1 };
            float2 o1 = { acc[mf][nf][2] + b0, acc[mf][nf][3] + b1 };
            if (roundOut) {
                o0.x = to_tf32(o0.x); o0.y = to_tf32(o0.y);
                o1.x = to_tf32(o1.x); o1.y = to_tf32(o1.y);
            }
            *(float2*)&Cmat[(size_t)row * N + col] = o0;
            *(float2*)&Cmat[(size_t)(row + 8) * N + col] = o1;
        }
    }
}

// ============================================================================
// Flash attention (causal), tf32 mma.sync, cp.async double-buffered K/V.
// Inputs in g_qkv are already tf32-rounded -> no cvt in the mainloop.
// ============================================================================
#define KS_STRIDE 68
#define VS_STRIDE 72
#define PS_STRIDE 36

__global__ __launch_bounds__(128) void attn_mma_kernel(const float* __restrict__ amask)
{
    __shared__ __align__(16) float Ks[2][32 * KS_STRIDE];
    __shared__ __align__(16) float Vs[2][32 * VS_STRIDE];
    __shared__ __align__(16) float Ps[64 * PS_STRIDE];
    __shared__ float Ams[2][32];

    const int qt = (gridDim.x - 1) - blockIdx.x;   // heavy CTAs first
    const int hh = blockIdx.y;
    const int bb = blockIdx.z;
    const int tid = threadIdx.x;
    const int lane = tid & 31;
    const int w = tid >> 5;
    const int r = lane >> 2;
    const int c = lane & 3;
    const int qbase = qt * 64;
    const int qlo = qbase + w * 16;

    const uint32_t ksb = smem_u32(&Ks[0][0]);
    const uint32_t vsb = smem_u32(&Vs[0][0]);

    // --- stage Q into the Ks region (values already tf32) ---
    float* Qstage = &Ks[0][0];
    for (int i = tid; i < 64 * 16; i += 128) {
        const int row = i >> 4;
        const int c4 = (i & 15) * 4;
        float4 v = *(const float4*)&g_qkv[(size_t)(bb * T_ + qbase + row) * C3_ + hh * D_ + c4];
        *(float4*)&Qstage[row * KS_STRIDE + c4] = v;
    }
    __syncthreads();

    uint32_t qa[8][4];
    #pragma unroll
    for (int kf = 0; kf < 8; kf++) {
        const int row = w * 16 + r;
        const int col = kf * 8 + c;
        qa[kf][0] = __float_as_uint(Qstage[row * KS_STRIDE + col]);
        qa[kf][1] = __float_as_uint(Qstage[(row + 8) * KS_STRIDE + col]);
        qa[kf][2] = __float_as_uint(Qstage[row * KS_STRIDE + col + 4]);
        qa[kf][3] = __float_as_uint(Qstage[(row + 8) * KS_STRIDE + col + 4]);
    }
    __syncthreads();

    const int nkt = 2 * qt + 2;

    // --- prologue: tile 0 -> buf 0 ---
    {
        const size_t rb = (size_t)(bb * T_) * C3_ + hh * D_;
        for (int idx = tid; idx < 512; idx += 128) {
            const int row = idx >> 4;
            const int c4 = (idx & 15) * 4;
            const float* gk = &g_qkv[rb + (size_t)row * C3_ + C_ + c4];
            cp_async16(ksb + (uint32_t)(row * KS_STRIDE + c4) * 4u, gk);
            cp_async16(vsb + (uint32_t)(row * VS_STRIDE + c4) * 4u, gk + C_);
        }
        if (tid < 32) Ams[0][tid] = amask[bb * T_ + tid];
        CP_COMMIT();
    }

    float o[8][4];
    #pragma unroll
    for (int nb = 0; nb < 8; nb++)
        #pragma unroll
        for (int j = 0; j < 4; j++) o[nb][j] = 0.f;
    float mrow[2] = { -INFINITY, -INFINITY };
    float lrow[2] = { 0.f, 0.f };

    for (int kt = 0; kt < nkt; kt++) {
        const int buf = kt & 1;
        const int kbase = kt * 32;
        const bool more = (kt + 1) < nkt;

        if (more) {
            const int nb2 = buf ^ 1;
            const size_t rb = (size_t)(bb * T_ + kbase + 32) * C3_ + hh * D_;
            const uint32_t kdst = ksb + (uint32_t)(nb2 * 32 * KS_STRIDE) * 4u;
            const uint32_t vdst = vsb + (uint32_t)(nb2 * 32 * VS_STRIDE) * 4u;
            for (int idx = tid; idx < 512; idx += 128) {
                const int row = idx >> 4;
                const int c4 = (idx & 15) * 4;
                const float* gk = &g_qkv[rb + (size_t)row * C3_ + C_ + c4];
                cp_async16(kdst + (uint32_t)(row * KS_STRIDE + c4) * 4u, gk);
                cp_async16(vdst + (uint32_t)(row * VS_STRIDE + c4) * 4u, gk + C_);
            }
            if (tid < 32) Ams[nb2][tid] = amask[bb * T_ + kbase + 32 + tid];
            CP_COMMIT();
            CP_WAIT(1);
        } else {
            CP_WAIT(0);
        }
        __syncthreads();

        const bool act = (kbase <= qlo + 15);
        if (act) {
            const float* ksB = &Ks[buf][0];
            const float* vsB = &Vs[buf][0];

            // --- S = Q K^T ---
            float s[4][4];
            #pragma unroll
            for (int nb = 0; nb < 4; nb++)
                #pragma unroll
                for (int j = 0; j < 4; j++) s[nb][j] = 0.f;
            #pragma unroll
            for (int kf = 0; kf < 8; kf++) {
                #pragma unroll
                for (int nb = 0; nb < 4; nb++) {
                    uint32_t bf[2];
                    bf[0] = __float_as_uint(ksB[(nb * 8 + r) * KS_STRIDE + kf * 8 + c]);
                    bf[1] = __float_as_uint(ksB[(nb * 8 + r) * KS_STRIDE + kf * 8 + c + 4]);
                    mma_tf32(s[nb], qa[kf], bf);
                }
            }

            // --- scale + masks ---
            const bool needmask = (kbase + 31 > qlo);
            #pragma unroll
            for (int nb = 0; nb < 4; nb++) {
                const float a0 = Ams[buf][nb * 8 + 2 * c];
                const float a1 = Ams[buf][nb * 8 + 2 * c + 1];
                s[nb][0] = s[nb][0] * 0.125f + a0;
                s[nb][1] = s[nb][1] * 0.125f + a1;
                s[nb][2] = s[nb][2] * 0.125f + a0;
                s[nb][3] = s[nb][3] * 0.125f + a1;
                if (needmask) {
                    const int kc0 = kbase + nb * 8 + 2 * c;
                    const int q0 = qlo + r;
                    if (kc0 > q0)         s[nb][0] = -INFINITY;
                    if (kc0 + 1 > q0)     s[nb][1] = -INFINITY;
                    if (kc0 > q0 + 8)     s[nb][2] = -INFINITY;
                    if (kc0 + 1 > q0 + 8) s[nb][3] = -INFINITY;
                }
            }

            __syncwarp();

            // --- online softmax ---
            #pragma unroll
            for (int hf = 0; hf < 2; hf++) {
                float mx = -INFINITY;
                #pragma unroll
                for (int nb = 0; nb < 4; nb++)
                    mx = fmaxf(mx, fmaxf(s[nb][2 * hf], s[nb][2 * hf + 1]));
                mx = fmaxf(mx, __shfl_xor_sync(0xffffffffu, mx, 1));
                mx = fmaxf(mx, __shfl_xor_sync(0xffffffffu, mx, 2));
                const float mnew = fmaxf(mrow[hf], mx);
                const float corr = __expf(mrow[hf] - mnew);
                float sum = 0.f;
                const int prow = w * 16 + r + 8 * hf;
                #pragma unroll
                for (int nb = 0; nb < 4; nb++) {
                    const float p0 = __expf(s[nb][2 * hf] - mnew);
                    const float p1 = __expf(s[nb][2 * hf + 1] - mnew);
                    sum += p0 + p1;
                    Ps[prow * PS_STRIDE + nb * 8 + 2 * c]     = to_tf32(p0);
                    Ps[prow * PS_STRIDE + nb * 8 + 2 * c + 1] = to_tf32(p1);
                }
                sum += __shfl_xor_sync(0xffffffffu, sum, 1);
                sum += __shfl_xor_sync(0xffffffffu, sum, 2);
                lrow[hf] = lrow[hf] * corr + sum;
                mrow[hf] = mnew;
                #pragma unroll
                for (int nb = 0; nb < 8; nb++) {
                    o[nb][2 * hf]     *= corr;
                    o[nb][2 * hf + 1] *= corr;
                }
            }
            __syncwarp();

            // --- O += P V ---
            #pragma unroll
            for (int kf = 0; kf < 4; kf++) {
                uint32_t pa[4];
                const int prow = w * 16 + r;
                pa[0] = __float_as_uint(Ps[prow * PS_STRIDE + kf * 8 + c]);
                pa[1] = __float_as_uint(Ps[(prow + 8) * PS_STRIDE + kf * 8 + c]);
                pa[2] = __float_as_uint(Ps[prow * PS_STRIDE + kf * 8 + c + 4]);
                pa[3] = __float_as_uint(Ps[(prow + 8) * PS_STRIDE + kf * 8 + c + 4]);
                #pragma unroll
                for (int nb = 0; nb < 8; nb++) {
                    uint32_t bf[2];
                    bf[0] = __float_as_uint(vsB[(kf * 8 + c) * VS_STRIDE + nb * 8 + r]);
                    bf[1] = __float_as_uint(vsB[(kf * 8 + c + 4) * VS_STRIDE + nb * 8 + r]);
                    mma_tf32(o[nb], pa, bf);
                }
            }
        }
        __syncthreads();
    }

    // --- epilogue: write g_y tf32-rounded (proj GEMM reads it pre-rounded) ---
    const float inv0 = 1.f / lrow[0];
    const float inv1 = 1.f / lrow[1];
    const int row0 = bb * T_ + qbase + w * 16 + r;
    #pragma unroll
    for (int nb = 0; nb < 8; nb++) {
        const int col = hh * D_ + nb * 8 + 2 * c;
        float2 v0 = { to_tf32(o[nb][0] * inv0), to_tf32(o[nb][1] * inv0) };
        float2 v1 = { to_tf32(o[nb][2] * inv1), to_tf32(o[nb][3] * inv1) };
        *(float2*)&g_y[(size_t)row0 * C_ + col] = v0;
        *(float2*)&g_y[(size_t)(row0 + 8) * C_ + col] = v1;
    }
}

// ----------------------------------------------------------------------------
// Launch.  Inputs: 0 x, 1 attention_mask, 2 attention_bias, 3 W_attn,
//                  4 b_attn, 5 W_proj, 6 b_proj
// ----------------------------------------------------------------------------
extern "C" void kernel_launch(void* const* d_in, const int* in_sizes, int n_in,
                              void* d_out, int out_size)
{
    (void)in_sizes; (void)n_in; (void)out_size;
    const float* x      = (const float*)d_in[0];
    const float* amask  = (const float*)d_in[1];
    const float* W_attn = (const float*)d_in[3];
    const float* b_attn = (const float*)d_in[4];
    const float* W_proj = (const float*)d_in[5];
    const float* b_proj = (const float*)d_in[6];
    float* out = (float*)d_out;

    float *qkv_ptr = nullptr, *y_ptr = nullptr, *xr = nullptr, *wt1 = nullptr, *wt2 = nullptr;
    cudaGetSymbolAddress((void**)&qkv_ptr, g_qkv);
    cudaGetSymbolAddress((void**)&y_ptr, g_y);
    cudaGetSymbolAddress((void**)&xr, g_xr);
    cudaGetSymbolAddress((void**)&wt1, g_WT1);
    cudaGetSymbolAddress((void**)&wt2, g_WT2);

    cudaFuncSetAttribute(gemm_mma_kernel, cudaFuncAttributeMaxDynamicSharedMemorySize,
                         GEMM_SMEM_BYTES);

    // 0) Pre-round / pre-transpose operands
    round_tf32_kernel<<<(BT_ * C_) / (256 * 4), 256>>>(x, xr);
    transpose_tf32_kernel<<<dim3(C3_ / 32, C_ / 32), dim3(32, 8)>>>(W_attn, wt1, C_, C3_);
    transpose_tf32_kernel<<<dim3(C_ / 32, C_ / 32), dim3(32, 8)>>>(W_proj, wt2, C_, C_);

    // 1) QKV projection (output tf32-rounded for attention): 24 x 16 CTAs
    gemm_mma_kernel<<<dim3(C3_ / 128, BT_ / 256), 256, GEMM_SMEM_BYTES>>>(
        xr, wt1, b_attn, qkv_ptr, BT_, C3_, C_, 1);

    // 2) Causal flash attention (tensor cores, pipelined)
    attn_mma_kernel<<<dim3(T_ / 64, H_, B_), 128>>>(amask);

    // 3) Output projection (fp32 output): 8 x 16 CTAs
    gemm_mma_kernel<<<dim3(C_ / 128, BT_ / 256), 256, GEMM_SMEM_BYTES>>>(
        y_ptr, wt2, b_proj, out, BT_, C_, C_, 0);
}

// round 12
// speedup vs baseline: 1.0390x; 1.0390x over previous
#include <cuda_runtime.h>
#include <cstdint>
#include <math.h>

// Problem constants
#define B_  2
#define T_  2048
#define C_  1024
#define H_  16
#define D_  64
#define BT_ (B_*T_)          // 4096
#define C3_ (3*C_)           // 3072

// Scratch (device globals: allocation-guard safe)
__device__ float g_qkv[BT_ * C3_];   // (B*T, 3C), stored tf32-rounded
__device__ float g_y[BT_ * C_];      // (B*T, C), stored tf32-rounded
__device__ float g_xr[BT_ * C_];     // x, tf32-rounded
__device__ float g_WT1[C3_ * C_];    // W_attn^T, tf32-rounded
__device__ float g_WT2[C_ * C_];     // W_proj^T, tf32-rounded

__device__ __forceinline__ float to_tf32(float f) {
    uint32_t u;
    asm("cvt.rna.tf32.f32 %0, %1;" : "=r"(u) : "f"(f));
    return __uint_as_float(u);
}

__device__ __forceinline__ void mma_tf32(float* d, const uint32_t* a, const uint32_t* b) {
    asm volatile(
        "mma.sync.aligned.m16n8k8.row.col.f32.tf32.tf32.f32 "
        "{%0,%1,%2,%3}, {%4,%5,%6,%7}, {%8,%9}, {%0,%1,%2,%3};"
        : "+f"(d[0]), "+f"(d[1]), "+f"(d[2]), "+f"(d[3])
        : "r"(a[0]), "r"(a[1]), "r"(a[2]), "r"(a[3]), "r"(b[0]), "r"(b[1]));
}

__device__ __forceinline__ uint32_t smem_u32(const void* p) {
    uint32_t a;
    asm("{ .reg .u64 t; cvta.to.shared.u64 t, %1; cvt.u32.u64 %0, t; }" : "=r"(a) : "l"(p));
    return a;
}
__device__ __forceinline__ void cp_async16(uint32_t saddr, const void* g) {
    asm volatile("cp.async.cg.shared.global [%0], [%1], 16;" :: "r"(saddr), "l"(g));
}
#define CP_COMMIT()  asm volatile("cp.async.commit_group;" ::: "memory")
#define CP_WAIT(n)   asm volatile("cp.async.wait_group %0;" :: "n"(n) : "memory")

// ============================================================================
// Elementwise tf32 rounding (vectorized): out[i] = tf32(in[i])
// ============================================================================
__global__ void round_tf32_kernel(const float* __restrict__ in, float* __restrict__ out)
{
    const int i = (blockIdx.x * blockDim.x + threadIdx.x) * 4;
    float4 v = *(const float4*)&in[i];
    v.x = to_tf32(v.x); v.y = to_tf32(v.y);
    v.z = to_tf32(v.z); v.w = to_tf32(v.w);
    *(float4*)&out[i] = v;
}

// ============================================================================
// Transpose + tf32-round: out[n][k] = tf32(in[k][n]).
// ============================================================================
__global__ void transpose_tf32_kernel(const float* __restrict__ in, float* __restrict__ out,
                                      int R, int Cc)
{
    __shared__ float tile[32][33];
    const int bx = blockIdx.x * 32;
    const int by = blockIdx.y * 32;
    #pragma unroll
    for (int j = 0; j < 32; j += 8)
        tile[threadIdx.y + j][threadIdx.x] = in[(size_t)(by + threadIdx.y + j) * Cc + bx + threadIdx.x];
    __syncthreads();
    #pragma unroll
    for (int j = 0; j < 32; j += 8)
        out[(size_t)(bx + threadIdx.y + j) * R + by + threadIdx.x] =
            to_tf32(tile[threadIdx.x][threadIdx.y + j]);
}

// ============================================================================
// tf32 mma.sync GEMM (R10 proven version):
// Cmat[M,N] = A[M,K] @ BT[N,K]^T + bias[N]. Register double-buffer, BK=16.
// CTA tile 256x128, 256 threads = 8 warps as 4(m) x 2(n), warp tile 64x64.
// Smem layout [kq][row][4]: all accesses bank-conflict-free.
// ============================================================================
__global__ __launch_bounds__(256, 1) void gemm_mma_kernel(
    const float* __restrict__ A, const float* __restrict__ BT,
    const float* __restrict__ bias, float* __restrict__ Cmat,
    int M, int N, int K, int roundOut)
{
    __shared__ float As[2][4][256][4];   // [buf][kq][row][ic]  32KB
    __shared__ float Bs[2][4][128][4];   // 16KB

    const int tid  = threadIdx.x;
    const int lane = tid & 31;
    const int warp = tid >> 5;
    const int wr = warp >> 1;            // 0..3 -> m offset wr*64
    const int wc = warp & 1;             // 0..1 -> n offset wc*64
    const int g  = lane >> 2;            // 0..7
    const int kc = lane & 3;             // 0..3

    const int m0 = blockIdx.y * 256;
    const int n0 = blockIdx.x * 128;

    const int lm  = tid >> 2;            // 0..63
    const int lkq = tid & 3;             // 0..3

    float acc[4][8][4];
    #pragma unroll
    for (int mf = 0; mf < 4; mf++)
        #pragma unroll
        for (int nf = 0; nf < 8; nf++)
            #pragma unroll
            for (int r = 0; r < 4; r++) acc[mf][nf][r] = 0.f;

    const int nch = K >> 4;              // K/16

    // ---- prologue: chunk 0 -> buffer 0
    {
        #pragma unroll
        for (int it = 0; it < 4; it++) {
            const int m = lm + it * 64;
            *(float4*)&As[0][lkq][m][0] = *(const float4*)&A[(size_t)(m0 + m) * K + 4 * lkq];
        }
        #pragma unroll
        for (int it = 0; it < 2; it++) {
            const int n = lm + it * 64;
            *(float4*)&Bs[0][lkq][n][0] = *(const float4*)&BT[(size_t)(n0 + n) * K + 4 * lkq];
        }
    }
    __syncthreads();

    for (int icn = 0; icn < nch; icn++) {
        const int cur = icn & 1;

        float4 pa[4], pb[2];
        const bool more = (icn + 1) < nch;
        if (more) {
            const int k0 = (icn + 1) << 4;
            #pragma unroll
            for (int it = 0; it < 4; it++) {
                const int m = lm + it * 64;
                pa[it] = *(const float4*)&A[(size_t)(m0 + m) * K + k0 + 4 * lkq];
            }
            #pragma unroll
            for (int it = 0; it < 2; it++) {
                const int n = lm + it * 64;
                pb[it] = *(const float4*)&BT[(size_t)(n0 + n) * K + k0 + 4 * lkq];
            }
        }

        #pragma unroll
        for (int t = 0; t < 2; t++) {
            uint32_t bf[8][2];
            #pragma unroll
            for (int nf = 0; nf < 8; nf++) {
                const int n = wc * 64 + nf * 8 + g;
                bf[nf][0] = __float_as_uint(Bs[cur][2 * t + 0][n][kc]);
                bf[nf][1] = __float_as_uint(Bs[cur][2 * t + 1][n][kc]);
            }
            #pragma unroll
            for (int mf = 0; mf < 4; mf++) {
                const int m = wr * 64 + mf * 16 + g;
                uint32_t af[4];
                af[0] = __float_as_uint(As[cur][2 * t + 0][m][kc]);
                af[1] = __float_as_uint(As[cur][2 * t + 0][m + 8][kc]);
                af[2] = __float_as_uint(As[cur][2 * t + 1][m][kc]);
                af[3] = __float_as_uint(As[cur][2 * t + 1][m + 8][kc]);
                #pragma unroll
                for (int nf = 0; nf < 8; nf++)
                    mma_tf32(acc[mf][nf], af, bf[nf]);
            }
        }

        if (more) {
            const int nxt = cur ^ 1;
            #pragma unroll
            for (int it = 0; it < 4; it++) {
                const int m = lm + it * 64;
                *(float4*)&As[nxt][lkq][m][0] = pa[it];
            }
            #pragma unroll
            for (int it = 0; it < 2; it++) {
                const int n = lm + it * 64;
                *(float4*)&Bs[nxt][lkq][n][0] = pb[it];
            }
            __syncthreads();
        }
    }

    // ---- epilogue: acc -> gmem with bias
    #pragma unroll
    for (int mf = 0; mf < 4; mf++) {
        const int row = m0 + wr * 64 + mf * 16 + g;
        #pragma unroll
        for (int nf = 0; nf < 8; nf++) {
            const int col = n0 + wc * 64 + nf * 8 + kc * 2;
            const float b0 = bias[col];
            const float b1 = bias[col + 1];
            float2 o0 = { acc[mf][nf][0] + b0, acc[mf][nf][1] + b1 };
            float2 o1 = { acc[mf][nf][2] + b0, acc[mf][nf][3] + b1 };
            if (roundOut) {
                o0.x = to_tf32(o0.x); o0.y = to_tf32(o0.y);
                o1.x = to_tf32(o1.x); o1.y = to_tf32(o1.y);
            }
            *(float2*)&Cmat[(size_t)row * N + col] = o0;
            *(float2*)&Cmat[(size_t)(row + 8) * N + col] = o1;
        }
    }
}

// ============================================================================
// Flash attention (causal), tf32 mma.sync, cp.async double-buffered K/V.
// Q tile 128 rows/CTA, 4 warps x 32 q-rows each (K/V fragment loads amortized
// over 2x MMAs vs 16-row warps). K tile 32. Inputs pre-rounded tf32.
// ============================================================================
#define KS_STRIDE 68
#define VS_STRIDE 72
#define PS_STRIDE 36

__global__ __launch_bounds__(128) void attn_mma_kernel(const float* __restrict__ amask)
{
    __shared__ __align__(16) float Ks[2][32 * KS_STRIDE];   // also Q staging (4352 floats)
    __shared__ __align__(16) float Vs[2][32 * VS_STRIDE];
    __shared__ __align__(16) float Ps[128 * PS_STRIDE];
    __shared__ float Ams[2][32];

    const int qt = (gridDim.x - 1) - blockIdx.x;   // heavy CTAs first
    const int hh = blockIdx.y;
    const int bb = blockIdx.z;
    const int tid = threadIdx.x;
    const int lane = tid & 31;
    const int w = tid >> 5;
    const int r = lane >> 2;
    const int c = lane & 3;
    const int qbase = qt * 128;
    const int qlo = qbase + w * 32;   // warp's first q row

    const uint32_t ksb = smem_u32(&Ks[0][0]);
    const uint32_t vsb = smem_u32(&Vs[0][0]);

    // --- stage Q (2 passes of 64 rows through the Ks region), cache fragments ---
    float* Qstage = &Ks[0][0];   // 64 rows x stride 68 = 4352 floats (whole Ks)
    uint32_t qa[8][8];
    #pragma unroll
    for (int pass = 0; pass < 2; pass++) {
        for (int i = tid; i < 64 * 16; i += 128) {
            const int row = i >> 4;
            const int c4 = (i & 15) * 4;
            float4 v = *(const float4*)&g_qkv[
                (size_t)(bb * T_ + qbase + pass * 64 + row) * C3_ + hh * D_ + c4];
            *(float4*)&Qstage[row * KS_STRIDE + c4] = v;
        }
        __syncthreads();
        if ((w >> 1) == pass) {
            const int lr = (w & 1) * 32 + r;
            #pragma unroll
            for (int kf = 0; kf < 8; kf++) {
                const int col = kf * 8 + c;
                qa[kf][0] = __float_as_uint(Qstage[lr * KS_STRIDE + col]);
                qa[kf][1] = __float_as_uint(Qstage[(lr + 8) * KS_STRIDE + col]);
                qa[kf][2] = __float_as_uint(Qstage[lr * KS_STRIDE + col + 4]);
                qa[kf][3] = __float_as_uint(Qstage[(lr + 8) * KS_STRIDE + col + 4]);
                qa[kf][4] = __float_as_uint(Qstage[(lr + 16) * KS_STRIDE + col]);
                qa[kf][5] = __float_as_uint(Qstage[(lr + 24) * KS_STRIDE + col]);
                qa[kf][6] = __float_as_uint(Qstage[(lr + 16) * KS_STRIDE + col + 4]);
                qa[kf][7] = __float_as_uint(Qstage[(lr + 24) * KS_STRIDE + col + 4]);
            }
        }
        __syncthreads();
    }

    const int nkt = 4 * qt + 4;

    // --- prologue: tile 0 -> buf 0 ---
    {
        const size_t rb = (size_t)(bb * T_) * C3_ + hh * D_;
        for (int idx = tid; idx < 512; idx += 128) {
            const int row = idx >> 4;
            const int c4 = (idx & 15) * 4;
            const float* gk = &g_qkv[rb + (size_t)row * C3_ + C_ + c4];
            cp_async16(ksb + (uint32_t)(row * KS_STRIDE + c4) * 4u, gk);
            cp_async16(vsb + (uint32_t)(row * VS_STRIDE + c4) * 4u, gk + C_);
        }
        if (tid < 32) Ams[0][tid] = amask[bb * T_ + tid];
        CP_COMMIT();
    }

    float o[8][8];
    #pragma unroll
    for (int nb = 0; nb < 8; nb++)
        #pragma unroll
        for (int j = 0; j < 8; j++) o[nb][j] = 0.f;
    float mrow[4] = { -INFINITY, -INFINITY, -INFINITY, -INFINITY };
    float lrow[4] = { 0.f, 0.f, 0.f, 0.f };

    for (int kt = 0; kt < nkt; kt++) {
        const int buf = kt & 1;
        const int kbase = kt * 32;
        const bool more = (kt + 1) < nkt;

        if (more) {
            const int nb2 = buf ^ 1;
            const size_t rb = (size_t)(bb * T_ + kbase + 32) * C3_ + hh * D_;
            const uint32_t kdst = ksb + (uint32_t)(nb2 * 32 * KS_STRIDE) * 4u;
            const uint32_t vdst = vsb + (uint32_t)(nb2 * 32 * VS_STRIDE) * 4u;
            for (int idx = tid; idx < 512; idx += 128) {
                const int row = idx >> 4;
                const int c4 = (idx & 15) * 4;
                const float* gk = &g_qkv[rb + (size_t)row * C3_ + C_ + c4];
                cp_async16(kdst + (uint32_t)(row * KS_STRIDE + c4) * 4u, gk);
                cp_async16(vdst + (uint32_t)(row * VS_STRIDE + c4) * 4u, gk + C_);
            }
            if (tid < 32) Ams[nb2][tid] = amask[bb * T_ + kbase + 32 + tid];
            CP_COMMIT();
            CP_WAIT(1);
        } else {
            CP_WAIT(0);
        }
        __syncthreads();

        const bool act = (kbase <= qlo + 31);
        if (act) {
            const float* ksB = &Ks[buf][0];
            const float* vsB = &Vs[buf][0];

            // --- S = Q K^T  (32 q-rows x 32 keys per warp) ---
            float s[4][8];
            #pragma unroll
            for (int nb = 0; nb < 4; nb++)
                #pragma unroll
                for (int j = 0; j < 8; j++) s[nb][j] = 0.f;
            #pragma unroll
            for (int kf = 0; kf < 8; kf++) {
                #pragma unroll
                for (int nb = 0; nb < 4; nb++) {
                    uint32_t bf[2];
                    bf[0] = __float_as_uint(ksB[(nb * 8 + r) * KS_STRIDE + kf * 8 + c]);
                    bf[1] = __float_as_uint(ksB[(nb * 8 + r) * KS_STRIDE + kf * 8 + c + 4]);
                    mma_tf32(&s[nb][0], &qa[kf][0], bf);
                    mma_tf32(&s[nb][4], &qa[kf][4], bf);
                }
            }

            // --- scale + masks ---
            const bool needmask = (kbase + 31 > qlo);
            #pragma unroll
            for (int nb = 0; nb < 4; nb++) {
                const float a0 = Ams[buf][nb * 8 + 2 * c];
                const float a1 = Ams[buf][nb * 8 + 2 * c + 1];
                #pragma unroll
                for (int hf = 0; hf < 4; hf++) {
                    s[nb][2 * hf]     = s[nb][2 * hf]     * 0.125f + a0;
                    s[nb][2 * hf + 1] = s[nb][2 * hf + 1] * 0.125f + a1;
                }
                if (needmask) {
                    const int kc0 = kbase + nb * 8 + 2 * c;
                    const int q0 = qlo + r;
                    #pragma unroll
                    for (int hf = 0; hf < 4; hf++) {
                        if (kc0 > q0 + 8 * hf)     s[nb][2 * hf]     = -INFINITY;
                        if (kc0 + 1 > q0 + 8 * hf) s[nb][2 * hf + 1] = -INFINITY;
                    }
                }
            }

            __syncwarp();   // prev tile's P reads done before overwrite

            // --- online softmax (four 8-row groups per lane) ---
            #pragma unroll
            for (int hf = 0; hf < 4; hf++) {
                float mx = -INFINITY;
                #pragma unroll
                for (int nb = 0; nb < 4; nb++)
                    mx = fmaxf(mx, fmaxf(s[nb][2 * hf], s[nb][2 * hf + 1]));
                mx = fmaxf(mx, __shfl_xor_sync(0xffffffffu, mx, 1));
                mx = fmaxf(mx, __shfl_xor_sync(0xffffffffu, mx, 2));
                const float mnew = fmaxf(mrow[hf], mx);
                const float corr = __expf(mrow[hf] - mnew);
                float sum = 0.f;
                const int prow = w * 32 + r + 8 * hf;
                #pragma unroll
                for (int nb = 0; nb < 4; nb++) {
                    const float p0 = __expf(s[nb][2 * hf] - mnew);
                    const float p1 = __expf(s[nb][2 * hf + 1] - mnew);
                    sum += p0 + p1;
                    Ps[prow * PS_STRIDE + nb * 8 + 2 * c]     = to_tf32(p0);
                    Ps[prow * PS_STRIDE + nb * 8 + 2 * c + 1] = to_tf32(p1);
                }
                sum += __shfl_xor_sync(0xffffffffu, sum, 1);
                sum += __shfl_xor_sync(0xffffffffu, sum, 2);
                lrow[hf] = lrow[hf] * corr + sum;
                mrow[hf] = mnew;
                #pragma unroll
                for (int nb = 0; nb < 8; nb++) {
                    o[nb][2 * hf]     *= corr;
                    o[nb][2 * hf + 1] *= corr;
                }
            }
            __syncwarp();

            // --- O += P V ---
            #pragma unroll
            for (int kf = 0; kf < 4; kf++) {
                uint32_t pa[8];
                const int prow = w * 32 + r;
                pa[0] = __float_as_uint(Ps[prow * PS_STRIDE + kf * 8 + c]);
                pa[1] = __float_as_uint(Ps[(prow + 8) * PS_STRIDE + kf * 8 + c]);
                pa[2] = __float_as_uint(Ps[prow * PS_STRIDE + kf * 8 + c + 4]);
                pa[3] = __float_as_uint(Ps[(prow + 8) * PS_STRIDE + kf * 8 + c + 4]);
                pa[4] = __float_as_uint(Ps[(prow + 16) * PS_STRIDE + kf * 8 + c]);
                pa[5] = __float_as_uint(Ps[(prow + 24) * PS_STRIDE + kf * 8 + c]);
                pa[6] = __float_as_uint(Ps[(prow + 16) * PS_STRIDE + kf * 8 + c + 4]);
                pa[7] = __float_as_uint(Ps[(prow + 24) * PS_STRIDE + kf * 8 + c + 4]);
                #pragma unroll
                for (int nb = 0; nb < 8; nb++) {
                    uint32_t bf[2];
                    bf[0] = __float_as_uint(vsB[(kf * 8 + c) * VS_STRIDE + nb * 8 + r]);
                    bf[1] = __float_as_uint(vsB[(kf * 8 + c + 4) * VS_STRIDE + nb * 8 + r]);
                    mma_tf32(&o[nb][0], &pa[0], bf);
                    mma_tf32(&o[nb][4], &pa[4], bf);
                }
            }
        }
        __syncthreads();
    }

    // --- epilogue: write g_y tf32-rounded (proj GEMM reads it pre-rounded) ---
    float inv[4];
    #pragma unroll
    for (int hf = 0; hf < 4; hf++) inv[hf] = 1.f / lrow[hf];
    const int row0 = bb * T_ + qbase + w * 32 + r;
    #pragma unroll
    for (int nb = 0; nb < 8; nb++) {
        const int col = hh * D_ + nb * 8 + 2 * c;
        #pragma unroll
        for (int hf = 0; hf < 4; hf++) {
            float2 v = { to_tf32(o[nb][2 * hf] * inv[hf]),
                         to_tf32(o[nb][2 * hf + 1] * inv[hf]) };
            *(float2*)&g_y[(size_t)(row0 + 8 * hf) * C_ + col] = v;
        }
    }
}

// ----------------------------------------------------------------------------
// Launch.  Inputs: 0 x, 1 attention_mask, 2 attention_bias, 3 W_attn,
//                  4 b_attn, 5 W_proj, 6 b_proj
// ----------------------------------------------------------------------------
extern "C" void kernel_launch(void* const* d_in, const int* in_sizes, int n_in,
                              void* d_out, int out_size)
{
    (void)in_sizes; (void)n_in; (void)out_size;
    const float* x      = (const float*)d_in[0];
    const float* amask  = (const float*)d_in[1];
    const float* W_attn = (const float*)d_in[3];
    const float* b_attn = (const float*)d_in[4];
    const float* W_proj = (const float*)d_in[5];
    const float* b_proj = (const float*)d_in[6];
    float* out = (float*)d_out;

    float *qkv_ptr = nullptr, *y_ptr = nullptr, *xr = nullptr, *wt1 = nullptr, *wt2 = nullptr;
    cudaGetSymbolAddress((void**)&qkv_ptr, g_qkv);
    cudaGetSymbolAddress((void**)&y_ptr, g_y);
    cudaGetSymbolAddress((void**)&xr, g_xr);
    cudaGetSymbolAddress((void**)&wt1, g_WT1);
    cudaGetSymbolAddress((void**)&wt2, g_WT2);

    // 0) Pre-round / pre-transpose operands
    round_tf32_kernel<<<(BT_ * C_) / (256 * 4), 256>>>(x, xr);
    transpose_tf32_kernel<<<dim3(C3_ / 32, C_ / 32), dim3(32, 8)>>>(W_attn, wt1, C_, C3_);
    transpose_tf32_kernel<<<dim3(C_ / 32, C_ / 32), dim3(32, 8)>>>(W_proj, wt2, C_, C_);

    // 1) QKV projection (output tf32-rounded for attention): 24 x 16 CTAs
    gemm_mma_kernel<<<dim3(C3_ / 128, BT_ / 256), 256>>>(xr, wt1, b_attn, qkv_ptr, BT_, C3_, C_, 1);

    // 2) Causal flash attention (tensor cores, 128-row Q tiles)
    attn_mma_kernel<<<dim3(T_ / 128, H_, B_), 128>>>(amask);

    // 3) Output projection (fp32 output): 8 x 16 CTAs
    gemm_mma_kernel<<<dim3(C_ / 128, BT_ / 256), 256>>>(y_ptr, wt2, b_proj, out, BT_, C_, C_, 0);
}

// round 13
// speedup vs baseline: 1.6113x; 1.5508x over previous
#include <cuda_runtime.h>
#include <cuda_fp16.h>
#include <cstdint>
#include <math.h>

// Problem constants
#define B_  2
#define T_  2048
#define C_  1024
#define H_  16
#define D_  64
#define BT_ (B_*T_)          // 4096
#define C3_ (3*C_)           // 3072

// Scratch (device globals: allocation-guard safe)
__device__ float  g_qkv[BT_ * C3_];   // (B*T, 3C) float, tf32-rounded (attention input)
__device__ __half g_yh[BT_ * C_];     // attention output, fp16 (proj GEMM input)
__device__ __half g_xh[BT_ * C_];     // x, fp16
__device__ __half g_WT1h[C3_ * C_];   // W_attn^T, fp16
__device__ __half g_WT2h[C_ * C_];    // W_proj^T, fp16

__device__ __forceinline__ float to_tf32(float f) {
    uint32_t u;
    asm("cvt.rna.tf32.f32 %0, %1;" : "=r"(u) : "f"(f));
    return __uint_as_float(u);
}

__device__ __forceinline__ void mma_tf32(float* d, const uint32_t* a, const uint32_t* b) {
    asm volatile(
        "mma.sync.aligned.m16n8k8.row.col.f32.tf32.tf32.f32 "
        "{%0,%1,%2,%3}, {%4,%5,%6,%7}, {%8,%9}, {%0,%1,%2,%3};"
        : "+f"(d[0]), "+f"(d[1]), "+f"(d[2]), "+f"(d[3])
        : "r"(a[0]), "r"(a[1]), "r"(a[2]), "r"(a[3]), "r"(b[0]), "r"(b[1]));
}

__device__ __forceinline__ void mma_f16(float* d, const uint32_t* a, const uint32_t* b) {
    asm volatile(
        "mma.sync.aligned.m16n8k16.row.col.f32.f16.f16.f32 "
        "{%0,%1,%2,%3}, {%4,%5,%6,%7}, {%8,%9}, {%0,%1,%2,%3};"
        : "+f"(d[0]), "+f"(d[1]), "+f"(d[2]), "+f"(d[3])
        : "r"(a[0]), "r"(a[1]), "r"(a[2]), "r"(a[3]), "r"(b[0]), "r"(b[1]));
}

__device__ __forceinline__ uint32_t smem_u32(const void* p) {
    uint32_t a;
    asm("{ .reg .u64 t; cvta.to.shared.u64 t, %1; cvt.u32.u64 %0, t; }" : "=r"(a) : "l"(p));
    return a;
}
__device__ __forceinline__ void cp_async16(uint32_t saddr, const void* g) {
    asm volatile("cp.async.cg.shared.global [%0], [%1], 16;" :: "r"(saddr), "l"(g));
}
#define CP_COMMIT()  asm volatile("cp.async.commit_group;" ::: "memory")
#define CP_WAIT(n)   asm volatile("cp.async.wait_group %0;" :: "n"(n) : "memory")

// ============================================================================
// Elementwise fp16 conversion: out[i] = half(in[i])
// ============================================================================
__global__ void round_fp16_kernel(const float* __restrict__ in, __half* __restrict__ out)
{
    const int i = (blockIdx.x * blockDim.x + threadIdx.x) * 4;
    float4 v = *(const float4*)&in[i];
    __half2 h0 = __floats2half2_rn(v.x, v.y);
    __half2 h1 = __floats2half2_rn(v.z, v.w);
    *(uint2*)&out[i] = make_uint2(*(uint32_t*)&h0, *(uint32_t*)&h1);
}

// ============================================================================
// Transpose + fp16: out[n][k] = half(in[k][n]).  in: R x Cc float, out: Cc x R half.
// ============================================================================
__global__ void transpose_fp16_kernel(const float* __restrict__ in, __half* __restrict__ out,
                                      int R, int Cc)
{
    __shared__ float tile[32][33];
    const int bx = blockIdx.x * 32;
    const int by = blockIdx.y * 32;
    #pragma unroll
    for (int j = 0; j < 32; j += 8)
        tile[threadIdx.y + j][threadIdx.x] = in[(size_t)(by + threadIdx.y + j) * Cc + bx + threadIdx.x];
    __syncthreads();
    #pragma unroll
    for (int j = 0; j < 32; j += 8)
        out[(size_t)(bx + threadIdx.y + j) * R + by + threadIdx.x] =
            __float2half_rn(tile[threadIdx.x][threadIdx.y + j]);
}

// ============================================================================
// fp16 mma.sync GEMM:  Cmat[M,N] = A[M,K] @ BT[N,K]^T + bias[N]   (fp32 accum)
// A, BT: half. Register double-buffer, BK=32 (2 x k16 HMMA steps per chunk).
// CTA 256x128, 256 threads = 8 warps as 4(m) x 2(n), warp tile 64x64.
// Smem u32 layout, row stride 20 (16 used + 4 pad): fragment reads conflict-free
// (20g+kc distinct mod 32). Dynamic smem 61440 B.
//   A(buf,row,w) = buf*5120 + row*20 + w
//   B(buf,row,w) = 10240 + buf*2560 + row*20 + w
// ============================================================================
#define GEMM_SMEM_BYTES 61440

__global__ __launch_bounds__(256, 1) void gemm_f16_kernel(
    const __half* __restrict__ A, const __half* __restrict__ BT,
    const float* __restrict__ bias, float* __restrict__ Cmat,
    int M, int N, int K, int roundOut)
{
    extern __shared__ __align__(16) uint32_t sm[];

    const int tid  = threadIdx.x;
    const int lane = tid & 31;
    const int warp = tid >> 5;
    const int wr = warp >> 1;            // 0..3 -> m offset wr*64
    const int wc = warp & 1;             // 0..1 -> n offset wc*64
    const int g  = lane >> 2;            // 0..7
    const int kc = lane & 3;             // 0..3

    const int m0 = blockIdx.y * 256;
    const int n0 = blockIdx.x * 128;

    const int r4 = tid >> 2;             // 0..63 (load row group)
    const int uq = tid & 3;              // 0..3  (uint4 index within row chunk)

    float acc[4][8][4];
    #pragma unroll
    for (int mf = 0; mf < 4; mf++)
        #pragma unroll
        for (int nf = 0; nf < 8; nf++)
            #pragma unroll
            for (int r = 0; r < 4; r++) acc[mf][nf][r] = 0.f;

    const int nch = K >> 5;              // K/32

    // ---- prologue: chunk 0 -> buffer 0
    {
        #pragma unroll
        for (int it = 0; it < 4; it++) {
            const int row = r4 + it * 64;
            uint4 v = *(const uint4*)&A[(size_t)(m0 + row) * K + uq * 8];
            *(uint4*)&sm[row * 20 + uq * 4] = v;
        }
        #pragma unroll
        for (int it = 0; it < 2; it++) {
            const int row = r4 + it * 64;
            uint4 v = *(const uint4*)&BT[(size_t)(n0 + row) * K + uq * 8];
            *(uint4*)&sm[10240 + row * 20 + uq * 4] = v;
        }
    }
    __syncthreads();

    for (int icn = 0; icn < nch; icn++) {
        const int cur = icn & 1;

        uint4 pa[4], pb[2];
        const bool more = (icn + 1) < nch;
        if (more) {
            const int k0 = (icn + 1) << 5;
            #pragma unroll
            for (int it = 0; it < 4; it++) {
                const int row = r4 + it * 64;
                pa[it] = *(const uint4*)&A[(size_t)(m0 + row) * K + k0 + uq * 8];
            }
            #pragma unroll
            for (int it = 0; it < 2; it++) {
                const int row = r4 + it * 64;
                pb[it] = *(const uint4*)&BT[(size_t)(n0 + row) * K + k0 + uq * 8];
            }
        }

        const uint32_t* smA = &sm[cur * 5120];
        const uint32_t* smB = &sm[10240 + cur * 2560];

        #pragma unroll
        for (int t = 0; t < 2; t++) {
            const int kw = 8 * t + kc;
            uint32_t bf[8][2];
            #pragma unroll
            for (int nf = 0; nf < 8; nf++) {
                const int n = wc * 64 + nf * 8 + g;
                bf[nf][0] = smB[n * 20 + kw];
                bf[nf][1] = smB[n * 20 + kw + 4];
            }
            #pragma unroll
            for (int mf = 0; mf < 4; mf++) {
                const int m = wr * 64 + mf * 16 + g;
                uint32_t af[4];
                af[0] = smA[m * 20 + kw];
                af[1] = smA[(m + 8) * 20 + kw];
                af[2] = smA[m * 20 + kw + 4];
                af[3] = smA[(m + 8) * 20 + kw + 4];
                #pragma unroll
                for (int nf = 0; nf < 8; nf++)
                    mma_f16(acc[mf][nf], af, bf[nf]);
            }
        }

        if (more) {
            const int nxt = cur ^ 1;
            uint32_t* dA = &sm[nxt * 5120];
            uint32_t* dB = &sm[10240 + nxt * 2560];
            #pragma unroll
            for (int it = 0; it < 4; it++)
                *(uint4*)&dA[(r4 + it * 64) * 20 + uq * 4] = pa[it];
            #pragma unroll
            for (int it = 0; it < 2; it++)
                *(uint4*)&dB[(r4 + it * 64) * 20 + uq * 4] = pb[it];
            __syncthreads();
        }
    }

    // ---- epilogue: acc -> gmem with bias
    #pragma unroll
    for (int mf = 0; mf < 4; mf++) {
        const int row = m0 + wr * 64 + mf * 16 + g;
        #pragma unroll
        for (int nf = 0; nf < 8; nf++) {
            const int col = n0 + wc * 64 + nf * 8 + kc * 2;
            const float b0 = bias[col];
            const float b1 = bias[col + 1];
            float2 o0 = { acc[mf][nf][0] + b0, acc[mf][nf][1] + b1 };
            float2 o1 = { acc[mf][nf][2] + b0, acc[mf][nf][3] + b1 };
            if (roundOut) {
                o0.x = to_tf32(o0.x); o0.y = to_tf32(o0.y);
                o1.x = to_tf32(o1.x); o1.y = to_tf32(o1.y);
            }
            *(float2*)&Cmat[(size_t)row * N + col] = o0;
            *(float2*)&Cmat[(size_t)(row + 8) * N + col] = o1;
        }
    }
}

// ============================================================================
// Flash attention (causal), tf32 mma.sync, cp.async double-buffered K/V.
// (Proven R10 structure.) Inputs in g_qkv already tf32-rounded.
// Epilogue writes fp16 g_yh for the fp16 proj GEMM.
// ============================================================================
#define KS_STRIDE 68
#define VS_STRIDE 72
#define PS_STRIDE 36

__global__ __launch_bounds__(128) void attn_mma_kernel(const float* __restrict__ amask)
{
    __shared__ __align__(16) float Ks[2][32 * KS_STRIDE];
    __shared__ __align__(16) float Vs[2][32 * VS_STRIDE];
    __shared__ __align__(16) float Ps[64 * PS_STRIDE];
    __shared__ float Ams[2][32];

    const int qt = (gridDim.x - 1) - blockIdx.x;   // heavy CTAs first
    const int hh = blockIdx.y;
    const int bb = blockIdx.z;
    const int tid = threadIdx.x;
    const int lane = tid & 31;
    const int w = tid >> 5;
    const int r = lane >> 2;
    const int c = lane & 3;
    const int qbase = qt * 64;
    const int qlo = qbase + w * 16;

    const uint32_t ksb = smem_u32(&Ks[0][0]);
    const uint32_t vsb = smem_u32(&Vs[0][0]);

    // --- stage Q into the Ks region (values already tf32) ---
    float* Qstage = &Ks[0][0];
    for (int i = tid; i < 64 * 16; i += 128) {
        const int row = i >> 4;
        const int c4 = (i & 15) * 4;
        float4 v = *(const float4*)&g_qkv[(size_t)(bb * T_ + qbase + row) * C3_ + hh * D_ + c4];
        *(float4*)&Qstage[row * KS_STRIDE + c4] = v;
    }
    __syncthreads();

    uint32_t qa[8][4];
    #pragma unroll
    for (int kf = 0; kf < 8; kf++) {
        const int row = w * 16 + r;
        const int col = kf * 8 + c;
        qa[kf][0] = __float_as_uint(Qstage[row * KS_STRIDE + col]);
        qa[kf][1] = __float_as_uint(Qstage[(row + 8) * KS_STRIDE + col]);
        qa[kf][2] = __float_as_uint(Qstage[row * KS_STRIDE + col + 4]);
        qa[kf][3] = __float_as_uint(Qstage[(row + 8) * KS_STRIDE + col + 4]);
    }
    __syncthreads();

    const int nkt = 2 * qt + 2;

    // --- prologue: tile 0 -> buf 0 ---
    {
        const size_t rb = (size_t)(bb * T_) * C3_ + hh * D_;
        for (int idx = tid; idx < 512; idx += 128) {
            const int row = idx >> 4;
            const int c4 = (idx & 15) * 4;
            const float* gk = &g_qkv[rb + (size_t)row * C3_ + C_ + c4];
            cp_async16(ksb + (uint32_t)(row * KS_STRIDE + c4) * 4u, gk);
            cp_async16(vsb + (uint32_t)(row * VS_STRIDE + c4) * 4u, gk + C_);
        }
        if (tid < 32) Ams[0][tid] = amask[bb * T_ + tid];
        CP_COMMIT();
    }

    float o[8][4];
    #pragma unroll
    for (int nb = 0; nb < 8; nb++)
        #pragma unroll
        for (int j = 0; j < 4; j++) o[nb][j] = 0.f;
    float mrow[2] = { -INFINITY, -INFINITY };
    float lrow[2] = { 0.f, 0.f };

    for (int kt = 0; kt < nkt; kt++) {
        const int buf = kt & 1;
        const int kbase = kt * 32;
        const bool more = (kt + 1) < nkt;

        if (more) {
            const int nb2 = buf ^ 1;
            const size_t rb = (size_t)(bb * T_ + kbase + 32) * C3_ + hh * D_;
            const uint32_t kdst = ksb + (uint32_t)(nb2 * 32 * KS_STRIDE) * 4u;
            const uint32_t vdst = vsb + (uint32_t)(nb2 * 32 * VS_STRIDE) * 4u;
            for (int idx = tid; idx < 512; idx += 128) {
                const int row = idx >> 4;
                const int c4 = (idx & 15) * 4;
                const float* gk = &g_qkv[rb + (size_t)row * C3_ + C_ + c4];
                cp_async16(kdst + (uint32_t)(row * KS_STRIDE + c4) * 4u, gk);
                cp_async16(vdst + (uint32_t)(row * VS_STRIDE + c4) * 4u, gk + C_);
            }
            if (tid < 32) Ams[nb2][tid] = amask[bb * T_ + kbase + 32 + tid];
            CP_COMMIT();
            CP_WAIT(1);
        } else {
            CP_WAIT(0);
        }
        __syncthreads();

        const bool act = (kbase <= qlo + 15);
        if (act) {
            const float* ksB = &Ks[buf][0];
            const float* vsB = &Vs[buf][0];

            // --- S = Q K^T ---
            float s[4][4];
            #pragma unroll
            for (int nb = 0; nb < 4; nb++)
                #pragma unroll
                for (int j = 0; j < 4; j++) s[nb][j] = 0.f;
            #pragma unroll
            for (int kf = 0; kf < 8; kf++) {
                #pragma unroll
                for (int nb = 0; nb < 4; nb++) {
                    uint32_t bf[2];
                    bf[0] = __float_as_uint(ksB[(nb * 8 + r) * KS_STRIDE + kf * 8 + c]);
                    bf[1] = __float_as_uint(ksB[(nb * 8 + r) * KS_STRIDE + kf * 8 + c + 4]);
                    mma_tf32(s[nb], qa[kf], bf);
                }
            }

            // --- scale + masks ---
            const bool needmask = (kbase + 31 > qlo);
            #pragma unroll
            for (int nb = 0; nb < 4; nb++) {
                const float a0 = Ams[buf][nb * 8 + 2 * c];
                const float a1 = Ams[buf][nb * 8 + 2 * c + 1];
                s[nb][0] = s[nb][0] * 0.125f + a0;
                s[nb][1] = s[nb][1] * 0.125f + a1;
                s[nb][2] = s[nb][2] * 0.125f + a0;
                s[nb][3] = s[nb][3] * 0.125f + a1;
                if (needmask) {
                    const int kc0 = kbase + nb * 8 + 2 * c;
                    const int q0 = qlo + r;
                    if (kc0 > q0)         s[nb][0] = -INFINITY;
                    if (kc0 + 1 > q0)     s[nb][1] = -INFINITY;
                    if (kc0 > q0 + 8)     s[nb][2] = -INFINITY;
                    if (kc0 + 1 > q0 + 8) s[nb][3] = -INFINITY;
                }
            }

            __syncwarp();

            // --- online softmax ---
            #pragma unroll
            for (int hf = 0; hf < 2; hf++) {
                float mx = -INFINITY;
                #pragma unroll
                for (int nb = 0; nb < 4; nb++)
                    mx = fmaxf(mx, fmaxf(s[nb][2 * hf], s[nb][2 * hf + 1]));
                mx = fmaxf(mx, __shfl_xor_sync(0xffffffffu, mx, 1));
                mx = fmaxf(mx, __shfl_xor_sync(0xffffffffu, mx, 2));
                const float mnew = fmaxf(mrow[hf], mx);
                const float corr = __expf(mrow[hf] - mnew);
                float sum = 0.f;
                const int prow = w * 16 + r + 8 * hf;
                #pragma unroll
                for (int nb = 0; nb < 4; nb++) {
                    const float p0 = __expf(s[nb][2 * hf] - mnew);
                    const float p1 = __expf(s[nb][2 * hf + 1] - mnew);
                    sum += p0 + p1;
                    Ps[prow * PS_STRIDE + nb * 8 + 2 * c]     = to_tf32(p0);
                    Ps[prow * PS_STRIDE + nb * 8 + 2 * c + 1] = to_tf32(p1);
                }
                sum += __shfl_xor_sync(0xffffffffu, sum, 1);
                sum += __shfl_xor_sync(0xffffffffu, sum, 2);
                lrow[hf] = lrow[hf] * corr + sum;
                mrow[hf] = mnew;
                #pragma unroll
                for (int nb = 0; nb < 8; nb++) {
                    o[nb][2 * hf]     *= corr;
                    o[nb][2 * hf + 1] *= corr;
                }
            }
            __syncwarp();

            // --- O += P V ---
            #pragma unroll
            for (int kf = 0; kf < 4; kf++) {
                uint32_t pa[4];
                const int prow = w * 16 + r;
                pa[0] = __float_as_uint(Ps[prow * PS_STRIDE + kf * 8 + c]);
                pa[1] = __float_as_uint(Ps[(prow + 8) * PS_STRIDE + kf * 8 + c]);
                pa[2] = __float_as_uint(Ps[prow * PS_STRIDE + kf * 8 + c + 4]);
                pa[3] = __float_as_uint(Ps[(prow + 8) * PS_STRIDE + kf * 8 + c + 4]);
                #pragma unroll
                for (int nb = 0; nb < 8; nb++) {
                    uint32_t bf[2];
                    bf[0] = __float_as_uint(vsB[(kf * 8 + c) * VS_STRIDE + nb * 8 + r]);
                    bf[1] = __float_as_uint(vsB[(kf * 8 + c + 4) * VS_STRIDE + nb * 8 + r]);
                    mma_tf32(o[nb], pa, bf);
                }
            }
        }
        __syncthreads();
    }

    // --- epilogue: write fp16 g_yh (proj GEMM input) ---
    const float inv0 = 1.f / lrow[0];
    const float inv1 = 1.f / lrow[1];
    const int row0 = bb * T_ + qbase + w * 16 + r;
    #pragma unroll
    for (int nb = 0; nb < 8; nb++) {
        const int col = hh * D_ + nb * 8 + 2 * c;
        __half2 v0 = __floats2half2_rn(o[nb][0] * inv0, o[nb][1] * inv0);
        __half2 v1 = __floats2half2_rn(o[nb][2] * inv1, o[nb][3] * inv1);
        *(__half2*)&g_yh[(size_t)row0 * C_ + col] = v0;
        *(__half2*)&g_yh[(size_t)(row0 + 8) * C_ + col] = v1;
    }
}

// ----------------------------------------------------------------------------
// Launch.  Inputs: 0 x, 1 attention_mask, 2 attention_bias, 3 W_attn,
//                  4 b_attn, 5 W_proj, 6 b_proj
// ----------------------------------------------------------------------------
extern "C" void kernel_launch(void* const* d_in, const int* in_sizes, int n_in,
                              void* d_out, int out_size)
{
    (void)in_sizes; (void)n_in; (void)out_size;
    const float* x      = (const float*)d_in[0];
    const float* amask  = (const float*)d_in[1];
    const float* W_attn = (const float*)d_in[3];
    const float* b_attn = (const float*)d_in[4];
    const float* W_proj = (const float*)d_in[5];
    const float* b_proj = (const float*)d_in[6];
    float* out = (float*)d_out;

    float* qkv_ptr = nullptr;
    __half *yh = nullptr, *xh = nullptr, *wt1 = nullptr, *wt2 = nullptr;
    cudaGetSymbolAddress((void**)&qkv_ptr, g_qkv);
    cudaGetSymbolAddress((void**)&yh, g_yh);
    cudaGetSymbolAddress((void**)&xh, g_xh);
    cudaGetSymbolAddress((void**)&wt1, g_WT1h);
    cudaGetSymbolAddress((void**)&wt2, g_WT2h);

    cudaFuncSetAttribute(gemm_f16_kernel, cudaFuncAttributeMaxDynamicSharedMemorySize,
                         GEMM_SMEM_BYTES);

    // 0) Pre-convert operands to fp16
    round_fp16_kernel<<<(BT_ * C_) / (256 * 4), 256>>>(x, xh);
    transpose_fp16_kernel<<<dim3(C3_ / 32, C_ / 32), dim3(32, 8)>>>(W_attn, wt1, C_, C3_);
    transpose_fp16_kernel<<<dim3(C_ / 32, C_ / 32), dim3(32, 8)>>>(W_proj, wt2, C_, C_);

    // 1) QKV projection (fp16 in, fp32 accum, tf32-rounded float out for attention)
    gemm_f16_kernel<<<dim3(C3_ / 128, BT_ / 256), 256, GEMM_SMEM_BYTES>>>(
        xh, wt1, b_attn, qkv_ptr, BT_, C3_, C_, 1);

    // 2) Causal flash attention (tf32 tensor cores) -> fp16 g_yh
    attn_mma_kernel<<<dim3(T_ / 64, H_, B_), 128>>>(amask);

    // 3) Output projection (fp16 in, fp32 out)
    gemm_f16_kernel<<<dim3(C_ / 128, BT_ / 256), 256, GEMM_SMEM_BYTES>>>(
        yh, wt2, b_proj, out, BT_, C_, C_, 0);
}

// round 14
// speedup vs baseline: 2.0009x; 1.2418x over previous
#include <cuda_runtime.h>
#include <cuda_fp16.h>
#include <cstdint>
#include <math.h>

// Problem constants
#define B_  2
#define T_  2048
#define C_  1024
#define H_  16
#define D_  64
#define BT_ (B_*T_)          // 4096
#define C3_ (3*C_)           // 3072

// Scratch (device globals: allocation-guard safe)
__device__ __half g_qkvh[BT_ * C3_];    // Q,K thirds [t][3C] fp16 (V third unused)
__device__ __half g_vt[B_ * H_ * D_ * T_];  // V transposed [b][h][d][t] fp16
__device__ __half g_yh[BT_ * C_];       // attention output, fp16 (proj GEMM input)
__device__ __half g_xh[BT_ * C_];       // x, fp16
__device__ __half g_WT1h[C3_ * C_];     // W_attn^T, fp16
__device__ __half g_WT2h[C_ * C_];      // W_proj^T, fp16

__device__ __forceinline__ void mma_f16(float* d, const uint32_t* a, const uint32_t* b) {
    asm volatile(
        "mma.sync.aligned.m16n8k16.row.col.f32.f16.f16.f32 "
        "{%0,%1,%2,%3}, {%4,%5,%6,%7}, {%8,%9}, {%0,%1,%2,%3};"
        : "+f"(d[0]), "+f"(d[1]), "+f"(d[2]), "+f"(d[3])
        : "r"(a[0]), "r"(a[1]), "r"(a[2]), "r"(a[3]), "r"(b[0]), "r"(b[1]));
}

__device__ __forceinline__ uint32_t smem_u32(const void* p) {
    uint32_t a;
    asm("{ .reg .u64 t; cvta.to.shared.u64 t, %1; cvt.u32.u64 %0, t; }" : "=r"(a) : "l"(p));
    return a;
}
__device__ __forceinline__ void cp_async16(uint32_t saddr, const void* g) {
    asm volatile("cp.async.cg.shared.global [%0], [%1], 16;" :: "r"(saddr), "l"(g));
}
#define CP_COMMIT()  asm volatile("cp.async.commit_group;" ::: "memory")
#define CP_WAIT(n)   asm volatile("cp.async.wait_group %0;" :: "n"(n) : "memory")

__device__ __forceinline__ uint32_t pack_h2(float a, float b) {
    __half2 h = __floats2half2_rn(a, b);
    return *reinterpret_cast<uint32_t*>(&h);
}

// ============================================================================
// Elementwise fp16 conversion: out[i] = half(in[i])
// ============================================================================
__global__ void round_fp16_kernel(const float* __restrict__ in, __half* __restrict__ out)
{
    const int i = (blockIdx.x * blockDim.x + threadIdx.x) * 4;
    float4 v = *(const float4*)&in[i];
    __half2 h0 = __floats2half2_rn(v.x, v.y);
    __half2 h1 = __floats2half2_rn(v.z, v.w);
    *(uint2*)&out[i] = make_uint2(*(uint32_t*)&h0, *(uint32_t*)&h1);
}

// ============================================================================
// Transpose + fp16: out[n][k] = half(in[k][n]).
// ============================================================================
__global__ void transpose_fp16_kernel(const float* __restrict__ in, __half* __restrict__ out,
                                      int R, int Cc)
{
    __shared__ float tile[32][33];
    const int bx = blockIdx.x * 32;
    const int by = blockIdx.y * 32;
    #pragma unroll
    for (int j = 0; j < 32; j += 8)
        tile[threadIdx.y + j][threadIdx.x] = in[(size_t)(by + threadIdx.y + j) * Cc + bx + threadIdx.x];
    __syncthreads();
    #pragma unroll
    for (int j = 0; j < 32; j += 8)
        out[(size_t)(bx + threadIdx.y + j) * R + by + threadIdx.x] =
            __float2half_rn(tile[threadIdx.x][threadIdx.y + j]);
}

// ============================================================================
// fp16 mma.sync GEMM (R13 proven mainloop). mode 0: float out + bias (proj).
// mode 1: qkv epilogue — Q/K thirds -> g_qkvh fp16, V third -> g_vt transposed.
// ============================================================================
#define GEMM_SMEM_BYTES 61440

__global__ __launch_bounds__(256, 1) void gemm_f16_kernel(
    const __half* __restrict__ A, const __half* __restrict__ BT,
    const float* __restrict__ bias, float* __restrict__ Cmat,
    int M, int N, int K, int mode)
{
    extern __shared__ __align__(16) uint32_t sm[];

    const int tid  = threadIdx.x;
    const int lane = tid & 31;
    const int warp = tid >> 5;
    const int wr = warp >> 1;
    const int wc = warp & 1;
    const int g  = lane >> 2;
    const int kc = lane & 3;

    const int m0 = blockIdx.y * 256;
    const int n0 = blockIdx.x * 128;

    const int r4 = tid >> 2;
    const int uq = tid & 3;

    float acc[4][8][4];
    #pragma unroll
    for (int mf = 0; mf < 4; mf++)
        #pragma unroll
        for (int nf = 0; nf < 8; nf++)
            #pragma unroll
            for (int r = 0; r < 4; r++) acc[mf][nf][r] = 0.f;

    const int nch = K >> 5;

    {
        #pragma unroll
        for (int it = 0; it < 4; it++) {
            const int row = r4 + it * 64;
            uint4 v = *(const uint4*)&A[(size_t)(m0 + row) * K + uq * 8];
            *(uint4*)&sm[row * 20 + uq * 4] = v;
        }
        #pragma unroll
        for (int it = 0; it < 2; it++) {
            const int row = r4 + it * 64;
            uint4 v = *(const uint4*)&BT[(size_t)(n0 + row) * K + uq * 8];
            *(uint4*)&sm[10240 + row * 20 + uq * 4] = v;
        }
    }
    __syncthreads();

    for (int icn = 0; icn < nch; icn++) {
        const int cur = icn & 1;

        uint4 pa[4], pb[2];
        const bool more = (icn + 1) < nch;
        if (more) {
            const int k0 = (icn + 1) << 5;
            #pragma unroll
            for (int it = 0; it < 4; it++) {
                const int row = r4 + it * 64;
                pa[it] = *(const uint4*)&A[(size_t)(m0 + row) * K + k0 + uq * 8];
            }
            #pragma unroll
            for (int it = 0; it < 2; it++) {
                const int row = r4 + it * 64;
                pb[it] = *(const uint4*)&BT[(size_t)(n0 + row) * K + k0 + uq * 8];
            }
        }

        const uint32_t* smA = &sm[cur * 5120];
        const uint32_t* smB = &sm[10240 + cur * 2560];

        #pragma unroll
        for (int t = 0; t < 2; t++) {
            const int kw = 8 * t + kc;
            uint32_t bf[8][2];
            #pragma unroll
            for (int nf = 0; nf < 8; nf++) {
                const int n = wc * 64 + nf * 8 + g;
                bf[nf][0] = smB[n * 20 + kw];
                bf[nf][1] = smB[n * 20 + kw + 4];
            }
            #pragma unroll
            for (int mf = 0; mf < 4; mf++) {
                const int m = wr * 64 + mf * 16 + g;
                uint32_t af[4];
                af[0] = smA[m * 20 + kw];
                af[1] = smA[(m + 8) * 20 + kw];
                af[2] = smA[m * 20 + kw + 4];
                af[3] = smA[(m + 8) * 20 + kw + 4];
                #pragma unroll
                for (int nf = 0; nf < 8; nf++)
                    mma_f16(acc[mf][nf], af, bf[nf]);
            }
        }

        if (more) {
            const int nxt = cur ^ 1;
            uint32_t* dA = &sm[nxt * 5120];
            uint32_t* dB = &sm[10240 + nxt * 2560];
            #pragma unroll
            for (int it = 0; it < 4; it++)
                *(uint4*)&dA[(r4 + it * 64) * 20 + uq * 4] = pa[it];
            #pragma unroll
            for (int it = 0; it < 2; it++)
                *(uint4*)&dB[(r4 + it * 64) * 20 + uq * 4] = pb[it];
            __syncthreads();
        }
    }

    // ---- epilogue
    #pragma unroll
    for (int mf = 0; mf < 4; mf++) {
        const int row = m0 + wr * 64 + mf * 16 + g;
        #pragma unroll
        for (int nf = 0; nf < 8; nf++) {
            const int col = n0 + wc * 64 + nf * 8 + kc * 2;
            const float b0 = bias[col];
            const float b1 = bias[col + 1];
            float2 o0 = { acc[mf][nf][0] + b0, acc[mf][nf][1] + b1 };
            float2 o1 = { acc[mf][nf][2] + b0, acc[mf][nf][3] + b1 };
            if (mode == 1) {
                if (n0 < 2 * C_) {
                    __half2 h0 = __floats2half2_rn(o0.x, o0.y);
                    __half2 h1 = __floats2half2_rn(o1.x, o1.y);
                    *(__half2*)&g_qkvh[(size_t)row * C3_ + col] = h0;
                    *(__half2*)&g_qkvh[(size_t)(row + 8) * C3_ + col] = h1;
                } else {
                    const int b = row >> 11;
                    const int t = row & (T_ - 1);
                    const int hd = col - 2 * C_;
                    const int h = hd >> 6;
                    const int d = hd & 63;
                    const size_t base = (((size_t)b * H_ + h) * D_ + d) * T_ + t;
                    g_vt[base]          = __float2half_rn(o0.x);
                    g_vt[base + T_]     = __float2half_rn(o0.y);
                    g_vt[base + 8]      = __float2half_rn(o1.x);
                    g_vt[base + T_ + 8] = __float2half_rn(o1.y);
                }
            } else {
                *(float2*)&Cmat[(size_t)row * N + col] = o0;
                *(float2*)&Cmat[(size_t)(row + 8) * N + col] = o1;
            }
        }
    }
}

// ============================================================================
// Flash attention (causal), fp16 m16n8k16 mma.sync, fp32 accum & softmax.
// K from g_qkvh [t][3C] (K third), V from g_vt [b][h][d][t] (pre-transposed).
// cp.async double-buffered. Smem strides (u32): K/Q 36, Vt/P 20 (conflict-free).
// ============================================================================
#define KSU 36
#define VSU 20
#define PSU 20

__global__ __launch_bounds__(128) void attn_f16_kernel(const float* __restrict__ amask)
{
    __shared__ __align__(16) uint32_t Ks[2][32 * KSU];   // also Q staging (64*36 = 2304 u32)
    __shared__ __align__(16) uint32_t Vs[2][64 * VSU];   // Vt tiles [d][key]
    __shared__ __align__(16) uint32_t Ps[64 * PSU];
    __shared__ float Ams[2][32];

    const int qt = (gridDim.x - 1) - blockIdx.x;   // heavy CTAs first
    const int hh = blockIdx.y;
    const int bb = blockIdx.z;
    const int tid = threadIdx.x;
    const int lane = tid & 31;
    const int w = tid >> 5;
    const int r = lane >> 2;
    const int c = lane & 3;
    const int qbase = qt * 64;
    const int qlo = qbase + w * 16;

    const uint32_t ksb = smem_u32(&Ks[0][0]);
    const uint32_t vsb = smem_u32(&Vs[0][0]);

    // --- stage Q (fp16) into the Ks region, cache A-fragments ---
    uint32_t* Qstage = &Ks[0][0];
    for (int i = tid; i < 512; i += 128) {
        const int row = i >> 3;
        const int q = i & 7;
        uint4 v = *(const uint4*)&g_qkvh[(size_t)(bb * T_ + qbase + row) * C3_ + hh * D_ + q * 8];
        *(uint4*)&Qstage[row * KSU + q * 4] = v;
    }
    __syncthreads();

    uint32_t qa[4][4];
    #pragma unroll
    for (int kf = 0; kf < 4; kf++) {
        const int row = w * 16 + r;
        qa[kf][0] = Qstage[row * KSU + kf * 8 + c];
        qa[kf][1] = Qstage[(row + 8) * KSU + kf * 8 + c];
        qa[kf][2] = Qstage[row * KSU + kf * 8 + c + 4];
        qa[kf][3] = Qstage[(row + 8) * KSU + kf * 8 + c + 4];
    }
    __syncthreads();   // Q reads done before cp.async overwrites Ks

    const int nkt = 2 * qt + 2;
    const __half* kgbase = &g_qkvh[(size_t)(bb * T_) * C3_ + C_ + hh * D_];
    const __half* vgbase = &g_vt[(size_t)(bb * H_ + hh) * D_ * T_];

    // --- prologue: tile 0 -> buf 0 ---
    {
        for (int i = tid; i < 256; i += 128) {          // K: 32 rows x 8 chunks
            const int row = i >> 3;
            const int q = i & 7;
            cp_async16(ksb + (uint32_t)((row * KSU + q * 4) * 4),
                       kgbase + (size_t)row * C3_ + q * 8);
        }
        for (int i = tid; i < 256; i += 128) {          // Vt: 64 d-rows x 4 chunks
            const int d = i >> 2;
            const int q = i & 3;
            cp_async16(vsb + (uint32_t)((d * VSU + q * 4) * 4),
                       vgbase + (size_t)d * T_ + q * 8);
        }
        if (tid < 32) Ams[0][tid] = amask[bb * T_ + tid];
        CP_COMMIT();
    }

    float o[8][4];
    #pragma unroll
    for (int nb = 0; nb < 8; nb++)
        #pragma unroll
        for (int j = 0; j < 4; j++) o[nb][j] = 0.f;
    float mrow[2] = { -INFINITY, -INFINITY };
    float lrow[2] = { 0.f, 0.f };

    for (int kt = 0; kt < nkt; kt++) {
        const int buf = kt & 1;
        const int kbase = kt * 32;
        const bool more = (kt + 1) < nkt;

        if (more) {
            const int nb2 = buf ^ 1;
            const __half* kg = kgbase + (size_t)(kbase + 32) * C3_;
            const __half* vg = vgbase + kbase + 32;
            const uint32_t kdst = ksb + (uint32_t)(nb2 * 32 * KSU * 4);
            const uint32_t vdst = vsb + (uint32_t)(nb2 * 64 * VSU * 4);
            for (int i = tid; i < 256; i += 128) {
                const int row = i >> 3;
                const int q = i & 7;
                cp_async16(kdst + (uint32_t)((row * KSU + q * 4) * 4),
                           kg + (size_t)row * C3_ + q * 8);
            }
            for (int i = tid; i < 256; i += 128) {
                const int d = i >> 2;
                const int q = i & 3;
                cp_async16(vdst + (uint32_t)((d * VSU + q * 4) * 4),
                           vg + (size_t)d * T_ + q * 8);
            }
            if (tid < 32) Ams[nb2][tid] = amask[bb * T_ + kbase + 32 + tid];
            CP_COMMIT();
            CP_WAIT(1);
        } else {
            CP_WAIT(0);
        }
        __syncthreads();

        const bool act = (kbase <= qlo + 15);
        if (act) {
            const uint32_t* ksB = &Ks[buf][0];
            const uint32_t* vsB = &Vs[buf][0];

            // --- S = Q K^T  (m16 n32 k64, fp16, fp32 accum) ---
            float s[4][4];
            #pragma unroll
            for (int nb = 0; nb < 4; nb++)
                #pragma unroll
                for (int j = 0; j < 4; j++) s[nb][j] = 0.f;
            #pragma unroll
            for (int kf = 0; kf < 4; kf++) {
                #pragma unroll
                for (int nb = 0; nb < 4; nb++) {
                    uint32_t bf[2];
                    bf[0] = ksB[(nb * 8 + r) * KSU + kf * 8 + c];
                    bf[1] = ksB[(nb * 8 + r) * KSU + kf * 8 + c + 4];
                    mma_f16(s[nb], qa[kf], bf);
                }
            }

            // --- scale + masks ---
            const bool needmask = (kbase + 31 > qlo);
            #pragma unroll
            for (int nb = 0; nb < 4; nb++) {
                const float a0 = Ams[buf][nb * 8 + 2 * c];
                const float a1 = Ams[buf][nb * 8 + 2 * c + 1];
                s[nb][0] = s[nb][0] * 0.125f + a0;
                s[nb][1] = s[nb][1] * 0.125f + a1;
                s[nb][2] = s[nb][2] * 0.125f + a0;
                s[nb][3] = s[nb][3] * 0.125f + a1;
                if (needmask) {
                    const int kc0 = kbase + nb * 8 + 2 * c;
                    const int q0 = qlo + r;
                    if (kc0 > q0)         s[nb][0] = -INFINITY;
                    if (kc0 + 1 > q0)     s[nb][1] = -INFINITY;
                    if (kc0 > q0 + 8)     s[nb][2] = -INFINITY;
                    if (kc0 + 1 > q0 + 8) s[nb][3] = -INFINITY;
                }
            }

            __syncwarp();   // prev tile's P reads done before overwrite

            // --- online softmax ---
            #pragma unroll
            for (int hf = 0; hf < 2; hf++) {
                float mx = -INFINITY;
                #pragma unroll
                for (int nb = 0; nb < 4; nb++)
                    mx = fmaxf(mx, fmaxf(s[nb][2 * hf], s[nb][2 * hf + 1]));
                mx = fmaxf(mx, __shfl_xor_sync(0xffffffffu, mx, 1));
                mx = fmaxf(mx, __shfl_xor_sync(0xffffffffu, mx, 2));
                const float mnew = fmaxf(mrow[hf], mx);
                const float corr = __expf(mrow[hf] - mnew);
                float sum = 0.f;
                const int prow = w * 16 + r + 8 * hf;
                #pragma unroll
                for (int nb = 0; nb < 4; nb++) {
                    const float p0 = __expf(s[nb][2 * hf] - mnew);
                    const float p1 = __expf(s[nb][2 * hf + 1] - mnew);
                    sum += p0 + p1;
                    Ps[prow * PSU + nb * 4 + c] = pack_h2(p0, p1);
                }
                sum += __shfl_xor_sync(0xffffffffu, sum, 1);
                sum += __shfl_xor_sync(0xffffffffu, sum, 2);
                lrow[hf] = lrow[hf] * corr + sum;
                mrow[hf] = mnew;
                #pragma unroll
                for (int nb = 0; nb < 8; nb++) {
                    o[nb][2 * hf]     *= corr;
                    o[nb][2 * hf + 1] *= corr;
                }
            }
            __syncwarp();

            // --- O += P V  (m16 n64 k32, fp16) ---
            #pragma unroll
            for (int kf = 0; kf < 2; kf++) {
                uint32_t pa[4];
                const int prow = w * 16 + r;
                pa[0] = Ps[prow * PSU + kf * 8 + c];
                pa[1] = Ps[(prow + 8) * PSU + kf * 8 + c];
                pa[2] = Ps[prow * PSU + kf * 8 + c + 4];
                pa[3] = Ps[(prow + 8) * PSU + kf * 8 + c + 4];
                #pragma unroll
                for (int nb = 0; nb < 8; nb++) {
                    uint32_t bf[2];
                    bf[0] = vsB[(nb * 8 + r) * VSU + kf * 8 + c];
                    bf[1] = vsB[(nb * 8 + r) * VSU + kf * 8 + c + 4];
                    mma_f16(o[nb], pa, bf);
                }
            }
        }
        __syncthreads();
    }

    // --- epilogue: write fp16 g_yh (proj GEMM input) ---
    const float inv0 = 1.f / lrow[0];
    const float inv1 = 1.f / lrow[1];
    const int row0 = bb * T_ + qbase + w * 16 + r;
    #pragma unroll
    for (int nb = 0; nb < 8; nb++) {
        const int col = hh * D_ + nb * 8 + 2 * c;
        __half2 v0 = __floats2half2_rn(o[nb][0] * inv0, o[nb][1] * inv0);
        __half2 v1 = __floats2half2_rn(o[nb][2] * inv1, o[nb][3] * inv1);
        *(__half2*)&g_yh[(size_t)row0 * C_ + col] = v0;
        *(__half2*)&g_yh[(size_t)(row0 + 8) * C_ + col] = v1;
    }
}

// ----------------------------------------------------------------------------
// Launch.  Inputs: 0 x, 1 attention_mask, 2 attention_bias, 3 W_attn,
//                  4 b_attn, 5 W_proj, 6 b_proj
// ----------------------------------------------------------------------------
extern "C" void kernel_launch(void* const* d_in, const int* in_sizes, int n_in,
                              void* d_out, int out_size)
{
    (void)in_sizes; (void)n_in; (void)out_size;
    const float* x      = (const float*)d_in[0];
    const float* amask  = (const float*)d_in[1];
    const float* W_attn = (const float*)d_in[3];
    const float* b_attn = (const float*)d_in[4];
    const float* W_proj = (const float*)d_in[5];
    const float* b_proj = (const float*)d_in[6];
    float* out = (float*)d_out;

    __half *yh = nullptr, *xh = nullptr, *wt1 = nullptr, *wt2 = nullptr;
    cudaGetSymbolAddress((void**)&yh, g_yh);
    cudaGetSymbolAddress((void**)&xh, g_xh);
    cudaGetSymbolAddress((void**)&wt1, g_WT1h);
    cudaGetSymbolAddress((void**)&wt2, g_WT2h);

    cudaFuncSetAttribute(gemm_f16_kernel, cudaFuncAttributeMaxDynamicSharedMemorySize,
                         GEMM_SMEM_BYTES);

    // 0) Pre-convert operands to fp16
    round_fp16_kernel<<<(BT_ * C_) / (256 * 4), 256>>>(x, xh);
    transpose_fp16_kernel<<<dim3(C3_ / 32, C_ / 32), dim3(32, 8)>>>(W_attn, wt1, C_, C3_);
    transpose_fp16_kernel<<<dim3(C_ / 32, C_ / 32), dim3(32, 8)>>>(W_proj, wt2, C_, C_);

    // 1) QKV projection: Q/K -> g_qkvh fp16, V -> g_vt transposed fp16
    gemm_f16_kernel<<<dim3(C3_ / 128, BT_ / 256), 256, GEMM_SMEM_BYTES>>>(
        xh, wt1, b_attn, out /*unused*/, BT_, C3_, C_, 1);

    // 2) Causal flash attention (fp16 tensor cores) -> fp16 g_yh
    attn_f16_kernel<<<dim3(T_ / 64, H_, B_), 128>>>(amask);

    // 3) Output projection (fp16 in, fp32 out)
    gemm_f16_kernel<<<dim3(C_ / 128, BT_ / 256), 256, GEMM_SMEM_BYTES>>>(
        yh, wt2, b_proj, out, BT_, C_, C_, 0);
}

// round 15
// speedup vs baseline: 2.0169x; 1.0080x over previous
#include <cuda_runtime.h>
#include <cuda_fp16.h>
#include <cstdint>
#include <math.h>

// Problem constants
#define B_  2
#define T_  2048
#define C_  1024
#define H_  16
#define D_  64
#define BT_ (B_*T_)          // 4096
#define C3_ (3*C_)           // 3072

// Scratch (device globals: allocation-guard safe)
__device__ __half g_qkvh[BT_ * C3_];    // Q,K thirds [t][3C] fp16 (V third unused)
__device__ __half g_vt[B_ * H_ * D_ * T_];  // V transposed [b][h][d][t] fp16
__device__ __half g_yh[BT_ * C_];       // attention output, fp16 (proj GEMM input)
__device__ __half g_xh[BT_ * C_];       // x, fp16
__device__ __half g_WT1h[C3_ * C_];     // W_attn^T, fp16
__device__ __half g_WT2h[C_ * C_];      // W_proj^T, fp16

__device__ __forceinline__ void mma_f16(float* d, const uint32_t* a, const uint32_t* b) {
    asm volatile(
        "mma.sync.aligned.m16n8k16.row.col.f32.f16.f16.f32 "
        "{%0,%1,%2,%3}, {%4,%5,%6,%7}, {%8,%9}, {%0,%1,%2,%3};"
        : "+f"(d[0]), "+f"(d[1]), "+f"(d[2]), "+f"(d[3])
        : "r"(a[0]), "r"(a[1]), "r"(a[2]), "r"(a[3]), "r"(b[0]), "r"(b[1]));
}

__device__ __forceinline__ uint32_t smem_u32(const void* p) {
    uint32_t a;
    asm("{ .reg .u64 t; cvta.to.shared.u64 t, %1; cvt.u32.u64 %0, t; }" : "=r"(a) : "l"(p));
    return a;
}
__device__ __forceinline__ void cp_async16(uint32_t saddr, const void* g) {
    asm volatile("cp.async.cg.shared.global [%0], [%1], 16;" :: "r"(saddr), "l"(g));
}
#define CP_COMMIT()  asm volatile("cp.async.commit_group;" ::: "memory")
#define CP_WAIT(n)   asm volatile("cp.async.wait_group %0;" :: "n"(n) : "memory")

__device__ __forceinline__ uint32_t pack_h2(float a, float b) {
    __half2 h = __floats2half2_rn(a, b);
    return *reinterpret_cast<uint32_t*>(&h);
}

// ============================================================================
// Elementwise fp16 conversion: out[i] = half(in[i])
// ============================================================================
__global__ void round_fp16_kernel(const float* __restrict__ in, __half* __restrict__ out)
{
    const int i = (blockIdx.x * blockDim.x + threadIdx.x) * 4;
    float4 v = *(const float4*)&in[i];
    __half2 h0 = __floats2half2_rn(v.x, v.y);
    __half2 h1 = __floats2half2_rn(v.z, v.w);
    *(uint2*)&out[i] = make_uint2(*(uint32_t*)&h0, *(uint32_t*)&h1);
}

// ============================================================================
// Transpose + fp16: out[n][k] = half(in[k][n]).
// ============================================================================
__global__ void transpose_fp16_kernel(const float* __restrict__ in, __half* __restrict__ out,
                                      int R, int Cc)
{
    __shared__ float tile[32][33];
    const int bx = blockIdx.x * 32;
    const int by = blockIdx.y * 32;
    #pragma unroll
    for (int j = 0; j < 32; j += 8)
        tile[threadIdx.y + j][threadIdx.x] = in[(size_t)(by + threadIdx.y + j) * Cc + bx + threadIdx.x];
    __syncthreads();
    #pragma unroll
    for (int j = 0; j < 32; j += 8)
        out[(size_t)(bx + threadIdx.y + j) * R + by + threadIdx.x] =
            __float2half_rn(tile[threadIdx.x][threadIdx.y + j]);
}

// ============================================================================
// fp16 mma.sync GEMM. CTA tile 128x128, 128 threads = 4 warps as 2(m) x 2(n),
// warp tile 64x64, BK=32, register double-buffer. 2 CTAs/SM co-resident
// (barrier domains overlap: one CTA computes while the other syncs/loads).
// Smem u32 layout, row stride 20 (16 used + 4 pad), conflict-free:
//   A(buf,row,w) = buf*2560 + row*20 + w
//   B(buf,row,w) = 5120 + buf*2560 + row*20 + w      (40 KB static)
// mode 0: float out + bias (proj). mode 1: QKV epilogue (Q/K fp16, V transposed).
// ============================================================================
__global__ __launch_bounds__(128, 2) void gemm_f16_kernel(
    const __half* __restrict__ A, const __half* __restrict__ BT,
    const float* __restrict__ bias, float* __restrict__ Cmat,
    int M, int N, int K, int mode)
{
    __shared__ __align__(16) uint32_t sm[10240];

    const int tid  = threadIdx.x;
    const int lane = tid & 31;
    const int warp = tid >> 5;
    const int wr = warp >> 1;            // 0..1 -> m offset wr*64
    const int wc = warp & 1;             // 0..1 -> n offset wc*64
    const int g  = lane >> 2;            // 0..7
    const int kc = lane & 3;             // 0..3

    const int m0 = blockIdx.y * 128;
    const int n0 = blockIdx.x * 128;

    const int lrow = tid >> 2;           // 0..31 (load row group)
    const int uq = tid & 3;              // 0..3  (uint4 within 32-half row chunk)

    float acc[4][8][4];
    #pragma unroll
    for (int mf = 0; mf < 4; mf++)
        #pragma unroll
        for (int nf = 0; nf < 8; nf++)
            #pragma unroll
            for (int r = 0; r < 4; r++) acc[mf][nf][r] = 0.f;

    const int nch = K >> 5;              // K/32

    // ---- prologue: chunk 0 -> buffer 0 (4 uint4 A + 4 uint4 B per thread)
    {
        #pragma unroll
        for (int it = 0; it < 4; it++) {
            const int row = lrow + it * 32;
            uint4 va = *(const uint4*)&A[(size_t)(m0 + row) * K + uq * 8];
            *(uint4*)&sm[row * 20 + uq * 4] = va;
            uint4 vb = *(const uint4*)&BT[(size_t)(n0 + row) * K + uq * 8];
            *(uint4*)&sm[5120 + row * 20 + uq * 4] = vb;
        }
    }
    __syncthreads();

    for (int icn = 0; icn < nch; icn++) {
        const int cur = icn & 1;

        uint4 pa[4], pb[4];
        const bool more = (icn + 1) < nch;
        if (more) {
            const int k0 = (icn + 1) << 5;
            #pragma unroll
            for (int it = 0; it < 4; it++) {
                const int row = lrow + it * 32;
                pa[it] = *(const uint4*)&A[(size_t)(m0 + row) * K + k0 + uq * 8];
                pb[it] = *(const uint4*)&BT[(size_t)(n0 + row) * K + k0 + uq * 8];
            }
        }

        const uint32_t* smA = &sm[cur * 2560];
        const uint32_t* smB = &sm[5120 + cur * 2560];

        #pragma unroll
        for (int t = 0; t < 2; t++) {
            const int kw = 8 * t + kc;
            uint32_t bf[8][2];
            #pragma unroll
            for (int nf = 0; nf < 8; nf++) {
                const int n = wc * 64 + nf * 8 + g;
                bf[nf][0] = smB[n * 20 + kw];
                bf[nf][1] = smB[n * 20 + kw + 4];
            }
            #pragma unroll
            for (int mf = 0; mf < 4; mf++) {
                const int m = wr * 64 + mf * 16 + g;
                uint32_t af[4];
                af[0] = smA[m * 20 + kw];
                af[1] = smA[(m + 8) * 20 + kw];
                af[2] = smA[m * 20 + kw + 4];
                af[3] = smA[(m + 8) * 20 + kw + 4];
                #pragma unroll
                for (int nf = 0; nf < 8; nf++)
                    mma_f16(acc[mf][nf], af, bf[nf]);
            }
        }

        if (more) {
            const int nxt = cur ^ 1;
            __syncthreads();   // all reads of nxt (from chunk icn-1) done
            uint32_t* dA = &sm[nxt * 2560];
            uint32_t* dB = &sm[5120 + nxt * 2560];
            #pragma unroll
            for (int it = 0; it < 4; it++) {
                const int row = lrow + it * 32;
                *(uint4*)&dA[row * 20 + uq * 4] = pa[it];
                *(uint4*)&dB[row * 20 + uq * 4] = pb[it];
            }
            __syncthreads();
        }
    }

    // ---- epilogue
    #pragma unroll
    for (int mf = 0; mf < 4; mf++) {
        const int row = m0 + wr * 64 + mf * 16 + g;
        #pragma unroll
        for (int nf = 0; nf < 8; nf++) {
            const int col = n0 + wc * 64 + nf * 8 + kc * 2;
            const float b0 = bias[col];
            const float b1 = bias[col + 1];
            float2 o0 = { acc[mf][nf][0] + b0, acc[mf][nf][1] + b1 };
            float2 o1 = { acc[mf][nf][2] + b0, acc[mf][nf][3] + b1 };
            if (mode == 1) {
                if (col < 2 * C_) {
                    __half2 h0 = __floats2half2_rn(o0.x, o0.y);
                    __half2 h1 = __floats2half2_rn(o1.x, o1.y);
                    *(__half2*)&g_qkvh[(size_t)row * C3_ + col] = h0;
                    *(__half2*)&g_qkvh[(size_t)(row + 8) * C3_ + col] = h1;
                } else {
                    const int b = row >> 11;
                    const int t = row & (T_ - 1);
                    const int hd = col - 2 * C_;
                    const int h = hd >> 6;
                    const int d = hd & 63;
                    const size_t base = (((size_t)b * H_ + h) * D_ + d) * T_ + t;
                    g_vt[base]          = __float2half_rn(o0.x);
                    g_vt[base + T_]     = __float2half_rn(o0.y);
                    g_vt[base + 8]      = __float2half_rn(o1.x);
                    g_vt[base + T_ + 8] = __float2half_rn(o1.y);
                }
            } else {
                *(float2*)&Cmat[(size_t)row * N + col] = o0;
                *(float2*)&Cmat[(size_t)(row + 8) * N + col] = o1;
            }
        }
    }
}

// ============================================================================
// Flash attention (causal), fp16 m16n8k16 mma.sync, fp32 accum & softmax.
// (R14 proven version, unchanged.)
// ============================================================================
#define KSU 36
#define VSU 20
#define PSU 20

__global__ __launch_bounds__(128) void attn_f16_kernel(const float* __restrict__ amask)
{
    __shared__ __align__(16) uint32_t Ks[2][32 * KSU];
    __shared__ __align__(16) uint32_t Vs[2][64 * VSU];
    __shared__ __align__(16) uint32_t Ps[64 * PSU];
    __shared__ float Ams[2][32];

    const int qt = (gridDim.x - 1) - blockIdx.x;
    const int hh = blockIdx.y;
    const int bb = blockIdx.z;
    const int tid = threadIdx.x;
    const int lane = tid & 31;
    const int w = tid >> 5;
    const int r = lane >> 2;
    const int c = lane & 3;
    const int qbase = qt * 64;
    const int qlo = qbase + w * 16;

    const uint32_t ksb = smem_u32(&Ks[0][0]);
    const uint32_t vsb = smem_u32(&Vs[0][0]);

    uint32_t* Qstage = &Ks[0][0];
    for (int i = tid; i < 512; i += 128) {
        const int row = i >> 3;
        const int q = i & 7;
        uint4 v = *(const uint4*)&g_qkvh[(size_t)(bb * T_ + qbase + row) * C3_ + hh * D_ + q * 8];
        *(uint4*)&Qstage[row * KSU + q * 4] = v;
    }
    __syncthreads();

    uint32_t qa[4][4];
    #pragma unroll
    for (int kf = 0; kf < 4; kf++) {
        const int row = w * 16 + r;
        qa[kf][0] = Qstage[row * KSU + kf * 8 + c];
        qa[kf][1] = Qstage[(row + 8) * KSU + kf * 8 + c];
        qa[kf][2] = Qstage[row * KSU + kf * 8 + c + 4];
        qa[kf][3] = Qstage[(row + 8) * KSU + kf * 8 + c + 4];
    }
    __syncthreads();

    const int nkt = 2 * qt + 2;
    const __half* kgbase = &g_qkvh[(size_t)(bb * T_) * C3_ + C_ + hh * D_];
    const __half* vgbase = &g_vt[(size_t)(bb * H_ + hh) * D_ * T_];

    {
        for (int i = tid; i < 256; i += 128) {
            const int row = i >> 3;
            const int q = i & 7;
            cp_async16(ksb + (uint32_t)((row * KSU + q * 4) * 4),
                       kgbase + (size_t)row * C3_ + q * 8);
        }
        for (int i = tid; i < 256; i += 128) {
            const int d = i >> 2;
            const int q = i & 3;
            cp_async16(vsb + (uint32_t)((d * VSU + q * 4) * 4),
                       vgbase + (size_t)d * T_ + q * 8);
        }
        if (tid < 32) Ams[0][tid] = amask[bb * T_ + tid];
        CP_COMMIT();
    }

    float o[8][4];
    #pragma unroll
    for (int nb = 0; nb < 8; nb++)
        #pragma unroll
        for (int j = 0; j < 4; j++) o[nb][j] = 0.f;
    float mrow[2] = { -INFINITY, -INFINITY };
    float lrow[2] = { 0.f, 0.f };

    for (int kt = 0; kt < nkt; kt++) {
        const int buf = kt & 1;
        const int kbase = kt * 32;
        const bool more = (kt + 1) < nkt;

        if (more) {
            const int nb2 = buf ^ 1;
            const __half* kg = kgbase + (size_t)(kbase + 32) * C3_;
            const __half* vg = vgbase + kbase + 32;
            const uint32_t kdst = ksb + (uint32_t)(nb2 * 32 * KSU * 4);
            const uint32_t vdst = vsb + (uint32_t)(nb2 * 64 * VSU * 4);
            for (int i = tid; i < 256; i += 128) {
                const int row = i >> 3;
                const int q = i & 7;
                cp_async16(kdst + (uint32_t)((row * KSU + q * 4) * 4),
                           kg + (size_t)row * C3_ + q * 8);
            }
            for (int i = tid; i < 256; i += 128) {
                const int d = i >> 2;
                const int q = i & 3;
                cp_async16(vdst + (uint32_t)((d * VSU + q * 4) * 4),
                           vg + (size_t)d * T_ + q * 8);
            }
            if (tid < 32) Ams[nb2][tid] = amask[bb * T_ + kbase + 32 + tid];
            CP_COMMIT();
            CP_WAIT(1);
        } else {
            CP_WAIT(0);
        }
        __syncthreads();

        const bool act = (kbase <= qlo + 15);
        if (act) {
            const uint32_t* ksB = &Ks[buf][0];
            const uint32_t* vsB = &Vs[buf][0];

            float s[4][4];
            #pragma unroll
            for (int nb = 0; nb < 4; nb++)
                #pragma unroll
                for (int j = 0; j < 4; j++) s[nb][j] = 0.f;
            #pragma unroll
            for (int kf = 0; kf < 4; kf++) {
                #pragma unroll
                for (int nb = 0; nb < 4; nb++) {
                    uint32_t bf[2];
                    bf[0] = ksB[(nb * 8 + r) * KSU + kf * 8 + c];
                    bf[1] = ksB[(nb * 8 + r) * KSU + kf * 8 + c + 4];
                    mma_f16(s[nb], qa[kf], bf);
                }
            }

            const bool needmask = (kbase + 31 > qlo);
            #pragma unroll
            for (int nb = 0; nb < 4; nb++) {
                const float a0 = Ams[buf][nb * 8 + 2 * c];
                const float a1 = Ams[buf][nb * 8 + 2 * c + 1];
                s[nb][0] = s[nb][0] * 0.125f + a0;
                s[nb][1] = s[nb][1] * 0.125f + a1;
                s[nb][2] = s[nb][2] * 0.125f + a0;
                s[nb][3] = s[nb][3] * 0.125f + a1;
                if (needmask) {
                    const int kc0 = kbase + nb * 8 + 2 * c;
                    const int q0 = qlo + r;
                    if (kc0 > q0)         s[nb][0] = -INFINITY;
                    if (kc0 + 1 > q0)     s[nb][1] = -INFINITY;
                    if (kc0 > q0 + 8)     s[nb][2] = -INFINITY;
                    if (kc0 + 1 > q0 + 8) s[nb][3] = -INFINITY;
                }
            }

            __syncwarp();

            #pragma unroll
            for (int hf = 0; hf < 2; hf++) {
                float mx = -INFINITY;
                #pragma unroll
                for (int nb = 0; nb < 4; nb++)
                    mx = fmaxf(mx, fmaxf(s[nb][2 * hf], s[nb][2 * hf + 1]));
                mx = fmaxf(mx, __shfl_xor_sync(0xffffffffu, mx, 1));
                mx = fmaxf(mx, __shfl_xor_sync(0xffffffffu, mx, 2));
                const float mnew = fmaxf(mrow[hf], mx);
                const float corr = __expf(mrow[hf] - mnew);
                float sum = 0.f;
                const int prow = w * 16 + r + 8 * hf;
                #pragma unroll
                for (int nb = 0; nb < 4; nb++) {
                    const float p0 = __expf(s[nb][2 * hf] - mnew);
                    const float p1 = __expf(s[nb][2 * hf + 1] - mnew);
                    sum += p0 + p1;
                    Ps[prow * PSU + nb * 4 + c] = pack_h2(p0, p1);
                }
                sum += __shfl_xor_sync(0xffffffffu, sum, 1);
                sum += __shfl_xor_sync(0xffffffffu, sum, 2);
                lrow[hf] = lrow[hf] * corr + sum;
                mrow[hf] = mnew;
                #pragma unroll
                for (int nb = 0; nb < 8; nb++) {
                    o[nb][2 * hf]     *= corr;
                    o[nb][2 * hf + 1] *= corr;
                }
            }
            __syncwarp();

            #pragma unroll
            for (int kf = 0; kf < 2; kf++) {
                uint32_t pa[4];
                const int prow = w * 16 + r;
                pa[0] = Ps[prow * PSU + kf * 8 + c];
                pa[1] = Ps[(prow + 8) * PSU + kf * 8 + c];
                pa[2] = Ps[prow * PSU + kf * 8 + c + 4];
                pa[3] = Ps[(prow + 8) * PSU + kf * 8 + c + 4];
                #pragma unroll
                for (int nb = 0; nb < 8; nb++) {
                    uint32_t bf[2];
                    bf[0] = vsB[(nb * 8 + r) * VSU + kf * 8 + c];
                    bf[1] = vsB[(nb * 8 + r) * VSU + kf * 8 + c + 4];
                    mma_f16(o[nb], pa, bf);
                }
            }
        }
        __syncthreads();
    }

    const float inv0 = 1.f / lrow[0];
    const float inv1 = 1.f / lrow[1];
    const int row0 = bb * T_ + qbase + w * 16 + r;
    #pragma unroll
    for (int nb = 0; nb < 8; nb++) {
        const int col = hh * D_ + nb * 8 + 2 * c;
        __half2 v0 = __floats2half2_rn(o[nb][0] * inv0, o[nb][1] * inv0);
        __half2 v1 = __floats2half2_rn(o[nb][2] * inv1, o[nb][3] * inv1);
        *(__half2*)&g_yh[(size_t)row0 * C_ + col] = v0;
        *(__half2*)&g_yh[(size_t)(row0 + 8) * C_ + col] = v1;
    }
}

// ----------------------------------------------------------------------------
// Launch.  Inputs: 0 x, 1 attention_mask, 2 attention_bias, 3 W_attn,
//                  4 b_attn, 5 W_proj, 6 b_proj
// ----------------------------------------------------------------------------
extern "C" void kernel_launch(void* const* d_in, const int* in_sizes, int n_in,
                              void* d_out, int out_size)
{
    (void)in_sizes; (void)n_in; (void)out_size;
    const float* x      = (const float*)d_in[0];
    const float* amask  = (const float*)d_in[1];
    const float* W_attn = (const float*)d_in[3];
    const float* b_attn = (const float*)d_in[4];
    const float* W_proj = (const float*)d_in[5];
    const float* b_proj = (const float*)d_in[6];
    float* out = (float*)d_out;

    __half *yh = nullptr, *xh = nullptr, *wt1 = nullptr, *wt2 = nullptr;
    cudaGetSymbolAddress((void**)&yh, g_yh);
    cudaGetSymbolAddress((void**)&xh, g_xh);
    cudaGetSymbolAddress((void**)&wt1, g_WT1h);
    cudaGetSymbolAddress((void**)&wt2, g_WT2h);

    // 0) Pre-convert operands to fp16
    round_fp16_kernel<<<(BT_ * C_) / (256 * 4), 256>>>(x, xh);
    transpose_fp16_kernel<<<dim3(C3_ / 32, C_ / 32), dim3(32, 8)>>>(W_attn, wt1, C_, C3_);
    transpose_fp16_kernel<<<dim3(C_ / 32, C_ / 32), dim3(32, 8)>>>(W_proj, wt2, C_, C_);

    // 1) QKV projection: Q/K -> g_qkvh fp16, V -> g_vt transposed fp16
    gemm_f16_kernel<<<dim3(C3_ / 128, BT_ / 128), 128>>>(
        xh, wt1, b_attn, out /*unused*/, BT_, C3_, C_, 1);

    // 2) Causal flash attention (fp16 tensor cores) -> fp16 g_yh
    attn_f16_kernel<<<dim3(T_ / 64, H_, B_), 128>>>(amask);

    // 3) Output projection (fp16 in, fp32 out)
    gemm_f16_kernel<<<dim3(C_ / 128, BT_ / 128), 128>>>(
        yh, wt2, b_proj, out, BT_, C_, C_, 0);
}

// round 16
// speedup vs baseline: 2.0908x; 1.0366x over previous
#include <cuda_runtime.h>
#include <cuda_fp16.h>
#include <cstdint>
#include <math.h>

// Problem constants
#define B_  2
#define T_  2048
#define C_  1024
#define H_  16
#define D_  64
#define BT_ (B_*T_)          // 4096
#define C3_ (3*C_)           // 3072

// Scratch (device globals: allocation-guard safe)
__device__ __half g_qkvh[BT_ * C3_];    // Q,K thirds [t][3C] fp16 (V third unused)
__device__ __half g_vt[B_ * H_ * D_ * T_];  // V transposed [b][h][d][t] fp16
__device__ __half g_yh[BT_ * C_];       // attention output, fp16 (proj GEMM input)
__device__ __half g_xh[BT_ * C_];       // x, fp16
__device__ __half g_WT1h[C3_ * C_];     // W_attn^T, fp16
__device__ __half g_WT2h[C_ * C_];      // W_proj^T, fp16

__device__ __forceinline__ void mma_f16(float* d, const uint32_t* a, const uint32_t* b) {
    asm volatile(
        "mma.sync.aligned.m16n8k16.row.col.f32.f16.f16.f32 "
        "{%0,%1,%2,%3}, {%4,%5,%6,%7}, {%8,%9}, {%0,%1,%2,%3};"
        : "+f"(d[0]), "+f"(d[1]), "+f"(d[2]), "+f"(d[3])
        : "r"(a[0]), "r"(a[1]), "r"(a[2]), "r"(a[3]), "r"(b[0]), "r"(b[1]));
}

__device__ __forceinline__ uint32_t smem_u32(const void* p) {
    uint32_t a;
    asm("{ .reg .u64 t; cvta.to.shared.u64 t, %1; cvt.u32.u64 %0, t; }" : "=r"(a) : "l"(p));
    return a;
}
__device__ __forceinline__ void cp_async16(uint32_t saddr, const void* g) {
    asm volatile("cp.async.cg.shared.global [%0], [%1], 16;" :: "r"(saddr), "l"(g));
}
#define CP_COMMIT()  asm volatile("cp.async.commit_group;" ::: "memory")
#define CP_WAIT(n)   asm volatile("cp.async.wait_group %0;" :: "n"(n) : "memory")

__device__ __forceinline__ uint32_t pack_h2(float a, float b) {
    __half2 h = __floats2half2_rn(a, b);
    return *reinterpret_cast<uint32_t*>(&h);
}

// ============================================================================
// Elementwise fp16 conversion: out[i] = half(in[i])
// ============================================================================
__global__ void round_fp16_kernel(const float* __restrict__ in, __half* __restrict__ out)
{
    const int i = (blockIdx.x * blockDim.x + threadIdx.x) * 4;
    float4 v = *(const float4*)&in[i];
    __half2 h0 = __floats2half2_rn(v.x, v.y);
    __half2 h1 = __floats2half2_rn(v.z, v.w);
    *(uint2*)&out[i] = make_uint2(*(uint32_t*)&h0, *(uint32_t*)&h1);
}

// ============================================================================
// Transpose + fp16: out[n][k] = half(in[k][n]).
// ============================================================================
__global__ void transpose_fp16_kernel(const float* __restrict__ in, __half* __restrict__ out,
                                      int R, int Cc)
{
    __shared__ float tile[32][33];
    const int bx = blockIdx.x * 32;
    const int by = blockIdx.y * 32;
    #pragma unroll
    for (int j = 0; j < 32; j += 8)
        tile[threadIdx.y + j][threadIdx.x] = in[(size_t)(by + threadIdx.y + j) * Cc + bx + threadIdx.x];
    __syncthreads();
    #pragma unroll
    for (int j = 0; j < 32; j += 8)
        out[(size_t)(bx + threadIdx.y + j) * R + by + threadIdx.x] =
            __float2half_rn(tile[threadIdx.x][threadIdx.y + j]);
}

// ============================================================================
// fp16 mma.sync GEMM (R15 proven version, unchanged).
// CTA 128x128, 128 threads = 4 warps (2x2), warp tile 64x64, BK=32, 2 CTAs/SM.
// ============================================================================
__global__ __launch_bounds__(128, 2) void gemm_f16_kernel(
    const __half* __restrict__ A, const __half* __restrict__ BT,
    const float* __restrict__ bias, float* __restrict__ Cmat,
    int M, int N, int K, int mode)
{
    __shared__ __align__(16) uint32_t sm[10240];

    const int tid  = threadIdx.x;
    const int lane = tid & 31;
    const int warp = tid >> 5;
    const int wr = warp >> 1;
    const int wc = warp & 1;
    const int g  = lane >> 2;
    const int kc = lane & 3;

    const int m0 = blockIdx.y * 128;
    const int n0 = blockIdx.x * 128;

    const int lrow = tid >> 2;
    const int uq = tid & 3;

    float acc[4][8][4];
    #pragma unroll
    for (int mf = 0; mf < 4; mf++)
        #pragma unroll
        for (int nf = 0; nf < 8; nf++)
            #pragma unroll
            for (int r = 0; r < 4; r++) acc[mf][nf][r] = 0.f;

    const int nch = K >> 5;

    {
        #pragma unroll
        for (int it = 0; it < 4; it++) {
            const int row = lrow + it * 32;
            uint4 va = *(const uint4*)&A[(size_t)(m0 + row) * K + uq * 8];
            *(uint4*)&sm[row * 20 + uq * 4] = va;
            uint4 vb = *(const uint4*)&BT[(size_t)(n0 + row) * K + uq * 8];
            *(uint4*)&sm[5120 + row * 20 + uq * 4] = vb;
        }
    }
    __syncthreads();

    for (int icn = 0; icn < nch; icn++) {
        const int cur = icn & 1;

        uint4 pa[4], pb[4];
        const bool more = (icn + 1) < nch;
        if (more) {
            const int k0 = (icn + 1) << 5;
            #pragma unroll
            for (int it = 0; it < 4; it++) {
                const int row = lrow + it * 32;
                pa[it] = *(const uint4*)&A[(size_t)(m0 + row) * K + k0 + uq * 8];
                pb[it] = *(const uint4*)&BT[(size_t)(n0 + row) * K + k0 + uq * 8];
            }
        }

        const uint32_t* smA = &sm[cur * 2560];
        const uint32_t* smB = &sm[5120 + cur * 2560];

        #pragma unroll
        for (int t = 0; t < 2; t++) {
            const int kw = 8 * t + kc;
            uint32_t bf[8][2];
            #pragma unroll
            for (int nf = 0; nf < 8; nf++) {
                const int n = wc * 64 + nf * 8 + g;
                bf[nf][0] = smB[n * 20 + kw];
                bf[nf][1] = smB[n * 20 + kw + 4];
            }
            #pragma unroll
            for (int mf = 0; mf < 4; mf++) {
                const int m = wr * 64 + mf * 16 + g;
                uint32_t af[4];
                af[0] = smA[m * 20 + kw];
                af[1] = smA[(m + 8) * 20 + kw];
                af[2] = smA[m * 20 + kw + 4];
                af[3] = smA[(m + 8) * 20 + kw + 4];
                #pragma unroll
                for (int nf = 0; nf < 8; nf++)
                    mma_f16(acc[mf][nf], af, bf[nf]);
            }
        }

        if (more) {
            const int nxt = cur ^ 1;
            __syncthreads();
            uint32_t* dA = &sm[nxt * 2560];
            uint32_t* dB = &sm[5120 + nxt * 2560];
            #pragma unroll
            for (int it = 0; it < 4; it++) {
                const int row = lrow + it * 32;
                *(uint4*)&dA[row * 20 + uq * 4] = pa[it];
                *(uint4*)&dB[row * 20 + uq * 4] = pb[it];
            }
            __syncthreads();
        }
    }

    #pragma unroll
    for (int mf = 0; mf < 4; mf++) {
        const int row = m0 + wr * 64 + mf * 16 + g;
        #pragma unroll
        for (int nf = 0; nf < 8; nf++) {
            const int col = n0 + wc * 64 + nf * 8 + kc * 2;
            const float b0 = bias[col];
            const float b1 = bias[col + 1];
            float2 o0 = { acc[mf][nf][0] + b0, acc[mf][nf][1] + b1 };
            float2 o1 = { acc[mf][nf][2] + b0, acc[mf][nf][3] + b1 };
            if (mode == 1) {
                if (col < 2 * C_) {
                    __half2 h0 = __floats2half2_rn(o0.x, o0.y);
                    __half2 h1 = __floats2half2_rn(o1.x, o1.y);
                    *(__half2*)&g_qkvh[(size_t)row * C3_ + col] = h0;
                    *(__half2*)&g_qkvh[(size_t)(row + 8) * C3_ + col] = h1;
                } else {
                    const int b = row >> 11;
                    const int t = row & (T_ - 1);
                    const int hd = col - 2 * C_;
                    const int h = hd >> 6;
                    const int d = hd & 63;
                    const size_t base = (((size_t)b * H_ + h) * D_ + d) * T_ + t;
                    g_vt[base]          = __float2half_rn(o0.x);
                    g_vt[base + T_]     = __float2half_rn(o0.y);
                    g_vt[base + 8]      = __float2half_rn(o1.x);
                    g_vt[base + T_ + 8] = __float2half_rn(o1.y);
                }
            } else {
                *(float2*)&Cmat[(size_t)row * N + col] = o0;
                *(float2*)&Cmat[(size_t)(row + 8) * N + col] = o1;
            }
        }
    }
}

// ============================================================================
// Flash attention (causal), fp16 m16n8k16, fp32 accum & softmax.
// K-tile 64 (halved loop overhead vs 32). Q tile 64 (16 rows/warp, 4 warps).
// K from g_qkvh [t][3C], V from g_vt [b][h][d][t]. cp.async double-buffered.
// Smem strides (u32): K/Q 36, Vt 36, P 36 — all conflict-free (4r+c mod 32).
// Every tile is active for every warp; causal mask only on the diagonal tile.
// ============================================================================
#define KSU 36
#define VSU 36
#define PSU 36

__global__ __launch_bounds__(128) void attn_f16_kernel(const float* __restrict__ amask)
{
    __shared__ __align__(16) uint32_t Ks[2][64 * KSU];   // also Q staging (64*36)
    __shared__ __align__(16) uint32_t Vs[2][64 * VSU];   // Vt tiles [d][key]
    __shared__ __align__(16) uint32_t Ps[64 * PSU];
    __shared__ float Ams[2][64];

    const int qt = (gridDim.x - 1) - blockIdx.x;   // heavy CTAs first
    const int hh = blockIdx.y;
    const int bb = blockIdx.z;
    const int tid = threadIdx.x;
    const int lane = tid & 31;
    const int w = tid >> 5;
    const int r = lane >> 2;
    const int c = lane & 3;
    const int qbase = qt * 64;
    const int qlo = qbase + w * 16;

    const uint32_t ksb = smem_u32(&Ks[0][0]);
    const uint32_t vsb = smem_u32(&Vs[0][0]);

    // --- stage Q (fp16) into the Ks region, cache A-fragments ---
    uint32_t* Qstage = &Ks[0][0];
    for (int i = tid; i < 512; i += 128) {
        const int row = i >> 3;
        const int q = i & 7;
        uint4 v = *(const uint4*)&g_qkvh[(size_t)(bb * T_ + qbase + row) * C3_ + hh * D_ + q * 8];
        *(uint4*)&Qstage[row * KSU + q * 4] = v;
    }
    __syncthreads();

    uint32_t qa[4][4];
    #pragma unroll
    for (int kf = 0; kf < 4; kf++) {
        const int row = w * 16 + r;
        qa[kf][0] = Qstage[row * KSU + kf * 8 + c];
        qa[kf][1] = Qstage[(row + 8) * KSU + kf * 8 + c];
        qa[kf][2] = Qstage[row * KSU + kf * 8 + c + 4];
        qa[kf][3] = Qstage[(row + 8) * KSU + kf * 8 + c + 4];
    }
    __syncthreads();   // Q reads done before cp.async overwrites Ks

    const int nkt = qt + 1;
    const __half* kgbase = &g_qkvh[(size_t)(bb * T_) * C3_ + C_ + hh * D_];
    const __half* vgbase = &g_vt[(size_t)(bb * H_ + hh) * D_ * T_];

    // --- prologue: tile 0 -> buf 0 (64 keys) ---
    {
        for (int i = tid; i < 512; i += 128) {          // K: 64 rows x 8 chunks
            const int row = i >> 3;
            const int q = i & 7;
            cp_async16(ksb + (uint32_t)((row * KSU + q * 4) * 4),
                       kgbase + (size_t)row * C3_ + q * 8);
        }
        for (int i = tid; i < 512; i += 128) {          // Vt: 64 d-rows x 8 chunks
            const int d = i >> 3;
            const int q = i & 7;
            cp_async16(vsb + (uint32_t)((d * VSU + q * 4) * 4),
                       vgbase + (size_t)d * T_ + q * 8);
        }
        if (tid < 64) Ams[0][tid] = amask[bb * T_ + tid];
        CP_COMMIT();
    }

    float o[8][4];
    #pragma unroll
    for (int nb = 0; nb < 8; nb++)
        #pragma unroll
        for (int j = 0; j < 4; j++) o[nb][j] = 0.f;
    float mrow[2] = { -INFINITY, -INFINITY };
    float lrow[2] = { 0.f, 0.f };

    for (int kt = 0; kt < nkt; kt++) {
        const int buf = kt & 1;
        const int kbase = kt * 64;
        const bool more = (kt + 1) < nkt;

        if (more) {
            const int nb2 = buf ^ 1;
            const __half* kg = kgbase + (size_t)(kbase + 64) * C3_;
            const __half* vg = vgbase + kbase + 64;
            const uint32_t kdst = ksb + (uint32_t)(nb2 * 64 * KSU * 4);
            const uint32_t vdst = vsb + (uint32_t)(nb2 * 64 * VSU * 4);
            for (int i = tid; i < 512; i += 128) {
                const int row = i >> 3;
                const int q = i & 7;
                cp_async16(kdst + (uint32_t)((row * KSU + q * 4) * 4),
                           kg + (size_t)row * C3_ + q * 8);
            }
            for (int i = tid; i < 512; i += 128) {
                const int d = i >> 3;
                const int q = i & 7;
                cp_async16(vdst + (uint32_t)((d * VSU + q * 4) * 4),
                           vg + (size_t)d * T_ + q * 8);
            }
            if (tid < 64) Ams[nb2][tid] = amask[bb * T_ + kbase + 64 + tid];
            CP_COMMIT();
            CP_WAIT(1);
        } else {
            CP_WAIT(0);
        }
        __syncthreads();

        const uint32_t* ksB = &Ks[buf][0];
        const uint32_t* vsB = &Vs[buf][0];

        // --- S = Q K^T  (m16 n64 k64, fp16, fp32 accum) ---
        float s[8][4];
        #pragma unroll
        for (int nb = 0; nb < 8; nb++)
            #pragma unroll
            for (int j = 0; j < 4; j++) s[nb][j] = 0.f;
        #pragma unroll
        for (int kf = 0; kf < 4; kf++) {
            #pragma unroll
            for (int nb = 0; nb < 8; nb++) {
                uint32_t bf[2];
                bf[0] = ksB[(nb * 8 + r) * KSU + kf * 8 + c];
                bf[1] = ksB[(nb * 8 + r) * KSU + kf * 8 + c + 4];
                mma_f16(s[nb], qa[kf], bf);
            }
        }

        // --- scale + masks (causal mask only on diagonal tile) ---
        const bool needmask = (kt == nkt - 1);
        #pragma unroll
        for (int nb = 0; nb < 8; nb++) {
            const float a0 = Ams[buf][nb * 8 + 2 * c];
            const float a1 = Ams[buf][nb * 8 + 2 * c + 1];
            s[nb][0] = s[nb][0] * 0.125f + a0;
            s[nb][1] = s[nb][1] * 0.125f + a1;
            s[nb][2] = s[nb][2] * 0.125f + a0;
            s[nb][3] = s[nb][3] * 0.125f + a1;
            if (needmask) {
                const int kc0 = kbase + nb * 8 + 2 * c;
                const int q0 = qlo + r;
                if (kc0 > q0)         s[nb][0] = -INFINITY;
                if (kc0 + 1 > q0)     s[nb][1] = -INFINITY;
                if (kc0 > q0 + 8)     s[nb][2] = -INFINITY;
                if (kc0 + 1 > q0 + 8) s[nb][3] = -INFINITY;
            }
        }

        __syncwarp();   // prev tile's P reads done before overwrite

        // --- online softmax ---
        #pragma unroll
        for (int hf = 0; hf < 2; hf++) {
            float mx = -INFINITY;
            #pragma unroll
            for (int nb = 0; nb < 8; nb++)
                mx = fmaxf(mx, fmaxf(s[nb][2 * hf], s[nb][2 * hf + 1]));
            mx = fmaxf(mx, __shfl_xor_sync(0xffffffffu, mx, 1));
            mx = fmaxf(mx, __shfl_xor_sync(0xffffffffu, mx, 2));
            const float mnew = fmaxf(mrow[hf], mx);
            const float corr = __expf(mrow[hf] - mnew);
            float sum = 0.f;
            const int prow = w * 16 + r + 8 * hf;
            #pragma unroll
            for (int nb = 0; nb < 8; nb++) {
                const float p0 = __expf(s[nb][2 * hf] - mnew);
                const float p1 = __expf(s[nb][2 * hf + 1] - mnew);
                sum += p0 + p1;
                Ps[prow * PSU + nb * 4 + c] = pack_h2(p0, p1);
            }
            sum += __shfl_xor_sync(0xffffffffu, sum, 1);
            sum += __shfl_xor_sync(0xffffffffu, sum, 2);
            lrow[hf] = lrow[hf] * corr + sum;
            mrow[hf] = mnew;
            #pragma unroll
            for (int nb = 0; nb < 8; nb++) {
                o[nb][2 * hf]     *= corr;
                o[nb][2 * hf + 1] *= corr;
            }
        }
        __syncwarp();

        // --- O += P V  (m16 n64 k64, fp16) ---
        #pragma unroll
        for (int kf = 0; kf < 4; kf++) {
            uint32_t pa[4];
            const int prow = w * 16 + r;
            pa[0] = Ps[prow * PSU + kf * 8 + c];
            pa[1] = Ps[(prow + 8) * PSU + kf * 8 + c];
            pa[2] = Ps[prow * PSU + kf * 8 + c + 4];
            pa[3] = Ps[(prow + 8) * PSU + kf * 8 + c + 4];
            #pragma unroll
            for (int nb = 0; nb < 8; nb++) {
                uint32_t bf[2];
                bf[0] = vsB[(nb * 8 + r) * VSU + kf * 8 + c];
                bf[1] = vsB[(nb * 8 + r) * VSU + kf * 8 + c + 4];
                mma_f16(o[nb], pa, bf);
            }
        }
        __syncthreads();   // all reads of buf done before cp.async reuses it
    }

    // --- epilogue: write fp16 g_yh (proj GEMM input) ---
    const float inv0 = 1.f / lrow[0];
    const float inv1 = 1.f / lrow[1];
    const int row0 = bb * T_ + qbase + w * 16 + r;
    #pragma unroll
    for (int nb = 0; nb < 8; nb++) {
        const int col = hh * D_ + nb * 8 + 2 * c;
        __half2 v0 = __floats2half2_rn(o[nb][0] * inv0, o[nb][1] * inv0);
        __half2 v1 = __floats2half2_rn(o[nb][2] * inv1, o[nb][3] * inv1);
        *(__half2*)&g_yh[(size_t)row0 * C_ + col] = v0;
        *(__half2*)&g_yh[(size_t)(row0 + 8) * C_ + col] = v1;
    }
}

// ----------------------------------------------------------------------------
// Launch.  Inputs: 0 x, 1 attention_mask, 2 attention_bias, 3 W_attn,
//                  4 b_attn, 5 W_proj, 6 b_proj
// ----------------------------------------------------------------------------
extern "C" void kernel_launch(void* const* d_in, const int* in_sizes, int n_in,
                              void* d_out, int out_size)
{
    (void)in_sizes; (void)n_in; (void)out_size;
    const float* x      = (const float*)d_in[0];
    const float* amask  = (const float*)d_in[1];
    const float* W_attn = (const float*)d_in[3];
    const float* b_attn = (const float*)d_in[4];
    const float* W_proj = (const float*)d_in[5];
    const float* b_proj = (const float*)d_in[6];
    float* out = (float*)d_out;

    __half *yh = nullptr, *xh = nullptr, *wt1 = nullptr, *wt2 = nullptr;
    cudaGetSymbolAddress((void**)&yh, g_yh);
    cudaGetSymbolAddress((void**)&xh, g_xh);
    cudaGetSymbolAddress((void**)&wt1, g_WT1h);
    cudaGetSymbolAddress((void**)&wt2, g_WT2h);

    // 0) Pre-convert operands to fp16
    round_fp16_kernel<<<(BT_ * C_) / (256 * 4), 256>>>(x, xh);
    transpose_fp16_kernel<<<dim3(C3_ / 32, C_ / 32), dim3(32, 8)>>>(W_attn, wt1, C_, C3_);
    transpose_fp16_kernel<<<dim3(C_ / 32, C_ / 32), dim3(32, 8)>>>(W_proj, wt2, C_, C_);

    // 1) QKV projection: Q/K -> g_qkvh fp16, V -> g_vt transposed fp16
    gemm_f16_kernel<<<dim3(C3_ / 128, BT_ / 128), 128>>>(
        xh, wt1, b_attn, out /*unused*/, BT_, C3_, C_, 1);

    // 2) Causal flash attention (fp16 tensor cores, 64-key tiles) -> fp16 g_yh
    attn_f16_kernel<<<dim3(T_ / 64, H_, B_), 128>>>(amask);

    // 3) Output projection (fp16 in, fp32 out)
    gemm_f16_kernel<<<dim3(C_ / 128, BT_ / 128), 128>>>(
        yh, wt2, b_proj, out, BT_, C_, C_, 0);
}

// round 17
// speedup vs baseline: 2.1999x; 1.0522x over previous
#include <cuda_runtime.h>
#include <cuda_fp16.h>
#include <cstdint>
#include <math.h>

// Problem constants
#define B_  2
#define T_  2048
#define C_  1024
#define H_  16
#define D_  64
#define BT_ (B_*T_)          // 4096
#define C3_ (3*C_)           // 3072

// Scratch (device globals: allocation-guard safe)
__device__ __half g_qkvh[BT_ * C3_];    // Q,K thirds [t][3C] fp16 (V third unused)
__device__ __half g_vt[B_ * H_ * D_ * T_];  // V transposed [b][h][d][t] fp16
__device__ __half g_yh[BT_ * C_];       // attention output, fp16 (proj GEMM input)
__device__ __half g_xh[BT_ * C_];       // x, fp16
__device__ __half g_WT1h[C3_ * C_];     // W_attn^T, fp16
__device__ __half g_WT2h[C_ * C_];      // W_proj^T, fp16

__device__ __forceinline__ void mma_f16(float* d, const uint32_t* a, const uint32_t* b) {
    asm volatile(
        "mma.sync.aligned.m16n8k16.row.col.f32.f16.f16.f32 "
        "{%0,%1,%2,%3}, {%4,%5,%6,%7}, {%8,%9}, {%0,%1,%2,%3};"
        : "+f"(d[0]), "+f"(d[1]), "+f"(d[2]), "+f"(d[3])
        : "r"(a[0]), "r"(a[1]), "r"(a[2]), "r"(a[3]), "r"(b[0]), "r"(b[1]));
}

__device__ __forceinline__ uint32_t smem_u32(const void* p) {
    uint32_t a;
    asm("{ .reg .u64 t; cvta.to.shared.u64 t, %1; cvt.u32.u64 %0, t; }" : "=r"(a) : "l"(p));
    return a;
}
__device__ __forceinline__ void cp_async16(uint32_t saddr, const void* g) {
    asm volatile("cp.async.cg.shared.global [%0], [%1], 16;" :: "r"(saddr), "l"(g));
}
#define CP_COMMIT()  asm volatile("cp.async.commit_group;" ::: "memory")
#define CP_WAIT(n)   asm volatile("cp.async.wait_group %0;" :: "n"(n) : "memory")

__device__ __forceinline__ uint32_t pack_h2(float a, float b) {
    __half2 h = __floats2half2_rn(a, b);
    return *reinterpret_cast<uint32_t*>(&h);
}

// ============================================================================
// Elementwise fp16 conversion: out[i] = half(in[i])
// ============================================================================
__global__ void round_fp16_kernel(const float* __restrict__ in, __half* __restrict__ out)
{
    const int i = (blockIdx.x * blockDim.x + threadIdx.x) * 4;
    float4 v = *(const float4*)&in[i];
    __half2 h0 = __floats2half2_rn(v.x, v.y);
    __half2 h1 = __floats2half2_rn(v.z, v.w);
    *(uint2*)&out[i] = make_uint2(*(uint32_t*)&h0, *(uint32_t*)&h1);
}

// ============================================================================
// Transpose + fp16: out[n][k] = half(in[k][n]).
// ============================================================================
__global__ void transpose_fp16_kernel(const float* __restrict__ in, __half* __restrict__ out,
                                      int R, int Cc)
{
    __shared__ float tile[32][33];
    const int bx = blockIdx.x * 32;
    const int by = blockIdx.y * 32;
    #pragma unroll
    for (int j = 0; j < 32; j += 8)
        tile[threadIdx.y + j][threadIdx.x] = in[(size_t)(by + threadIdx.y + j) * Cc + bx + threadIdx.x];
    __syncthreads();
    #pragma unroll
    for (int j = 0; j < 32; j += 8)
        out[(size_t)(bx + threadIdx.y + j) * R + by + threadIdx.x] =
            __float2half_rn(tile[threadIdx.x][threadIdx.y + j]);
}

// ============================================================================
// fp16 mma.sync GEMM. CTA 128x128, 4 warps (2x2), warp tile 64x64, BK=32,
// 2 CTAs/SM, register double-buffer, SINGLE barrier per chunk.
// ============================================================================
__global__ __launch_bounds__(128, 2) void gemm_f16_kernel(
    const __half* __restrict__ A, const __half* __restrict__ BT,
    const float* __restrict__ bias, float* __restrict__ Cmat,
    int M, int N, int K, int mode)
{
    __shared__ __align__(16) uint32_t sm[10240];

    const int tid  = threadIdx.x;
    const int lane = tid & 31;
    const int warp = tid >> 5;
    const int wr = warp >> 1;
    const int wc = warp & 1;
    const int g  = lane >> 2;
    const int kc = lane & 3;

    const int m0 = blockIdx.y * 128;
    const int n0 = blockIdx.x * 128;

    const int lrow = tid >> 2;
    const int uq = tid & 3;

    float acc[4][8][4];
    #pragma unroll
    for (int mf = 0; mf < 4; mf++)
        #pragma unroll
        for (int nf = 0; nf < 8; nf++)
            #pragma unroll
            for (int r = 0; r < 4; r++) acc[mf][nf][r] = 0.f;

    const int nch = K >> 5;

    {
        #pragma unroll
        for (int it = 0; it < 4; it++) {
            const int row = lrow + it * 32;
            uint4 va = *(const uint4*)&A[(size_t)(m0 + row) * K + uq * 8];
            *(uint4*)&sm[row * 20 + uq * 4] = va;
            uint4 vb = *(const uint4*)&BT[(size_t)(n0 + row) * K + uq * 8];
            *(uint4*)&sm[5120 + row * 20 + uq * 4] = vb;
        }
    }
    __syncthreads();

    for (int icn = 0; icn < nch; icn++) {
        const int cur = icn & 1;

        uint4 pa[4], pb[4];
        const bool more = (icn + 1) < nch;
        if (more) {
            const int k0 = (icn + 1) << 5;
            #pragma unroll
            for (int it = 0; it < 4; it++) {
                const int row = lrow + it * 32;
                pa[it] = *(const uint4*)&A[(size_t)(m0 + row) * K + k0 + uq * 8];
                pb[it] = *(const uint4*)&BT[(size_t)(n0 + row) * K + k0 + uq * 8];
            }
        }

        const uint32_t* smA = &sm[cur * 2560];
        const uint32_t* smB = &sm[5120 + cur * 2560];

        #pragma unroll
        for (int t = 0; t < 2; t++) {
            const int kw = 8 * t + kc;
            uint32_t bf[8][2];
            #pragma unroll
            for (int nf = 0; nf < 8; nf++) {
                const int n = wc * 64 + nf * 8 + g;
                bf[nf][0] = smB[n * 20 + kw];
                bf[nf][1] = smB[n * 20 + kw + 4];
            }
            #pragma unroll
            for (int mf = 0; mf < 4; mf++) {
                const int m = wr * 64 + mf * 16 + g;
                uint32_t af[4];
                af[0] = smA[m * 20 + kw];
                af[1] = smA[(m + 8) * 20 + kw];
                af[2] = smA[m * 20 + kw + 4];
                af[3] = smA[(m + 8) * 20 + kw + 4];
                #pragma unroll
                for (int nf = 0; nf < 8; nf++)
                    mma_f16(acc[mf][nf], af, bf[nf]);
            }
        }

        if (more) {
            const int nxt = cur ^ 1;
            uint32_t* dA = &sm[nxt * 2560];
            uint32_t* dB = &sm[5120 + nxt * 2560];
            #pragma unroll
            for (int it = 0; it < 4; it++) {
                const int row = lrow + it * 32;
                *(uint4*)&dA[row * 20 + uq * 4] = pa[it];
                *(uint4*)&dB[row * 20 + uq * 4] = pb[it];
            }
            __syncthreads();   // single barrier per chunk (safe: see R13 ordering)
        }
    }

    #pragma unroll
    for (int mf = 0; mf < 4; mf++) {
        const int row = m0 + wr * 64 + mf * 16 + g;
        #pragma unroll
        for (int nf = 0; nf < 8; nf++) {
            const int col = n0 + wc * 64 + nf * 8 + kc * 2;
            const float b0 = bias[col];
            const float b1 = bias[col + 1];
            float2 o0 = { acc[mf][nf][0] + b0, acc[mf][nf][1] + b1 };
            float2 o1 = { acc[mf][nf][2] + b0, acc[mf][nf][3] + b1 };
            if (mode == 1) {
                if (col < 2 * C_) {
                    __half2 h0 = __floats2half2_rn(o0.x, o0.y);
                    __half2 h1 = __floats2half2_rn(o1.x, o1.y);
                    *(__half2*)&g_qkvh[(size_t)row * C3_ + col] = h0;
                    *(__half2*)&g_qkvh[(size_t)(row + 8) * C3_ + col] = h1;
                } else {
                    const int b = row >> 11;
                    const int t = row & (T_ - 1);
                    const int hd = col - 2 * C_;
                    const int h = hd >> 6;
                    const int d = hd & 63;
                    const size_t base = (((size_t)b * H_ + h) * D_ + d) * T_ + t;
                    g_vt[base]          = __float2half_rn(o0.x);
                    g_vt[base + T_]     = __float2half_rn(o0.y);
                    g_vt[base + 8]      = __float2half_rn(o1.x);
                    g_vt[base + T_ + 8] = __float2half_rn(o1.y);
                }
            } else {
                *(float2*)&Cmat[(size_t)row * N + col] = o0;
                *(float2*)&Cmat[(size_t)(row + 8) * N + col] = o1;
            }
        }
    }
}

// ============================================================================
// Flash attention (causal), fp16 m16n8k16, fp32 accum & softmax.
// K-tile 64, Q tile 64 (16 rows/warp, 4 warps). COMPLEMENTARY Q-TILE PAIRING:
// each CTA processes q-tiles (i, 31-i) sequentially -> constant 33 tiles/CTA,
// single perfectly balanced wave of 512 CTAs.
// ============================================================================
#define KSU 36
#define VSU 36
#define PSU 36
#define NQT (T_ / 64)   // 32 q-tiles

__global__ __launch_bounds__(128) void attn_f16_kernel(const float* __restrict__ amask)
{
    __shared__ __align__(16) uint32_t Ks[2][64 * KSU];
    __shared__ __align__(16) uint32_t Vs[2][64 * VSU];
    __shared__ __align__(16) uint32_t Ps[64 * PSU];
    __shared__ float Ams[2][64];

    const int pairIdx = blockIdx.x;   // 0..15
    const int hh = blockIdx.y;
    const int bb = blockIdx.z;
    const int tid = threadIdx.x;
    const int lane = tid & 31;
    const int w = tid >> 5;
    const int r = lane >> 2;
    const int c = lane & 3;

    const uint32_t ksb = smem_u32(&Ks[0][0]);
    const uint32_t vsb = smem_u32(&Vs[0][0]);
    const __half* kgbase = &g_qkvh[(size_t)(bb * T_) * C3_ + C_ + hh * D_];
    const __half* vgbase = &g_vt[(size_t)(bb * H_ + hh) * D_ * T_];

    #pragma unroll 1
    for (int pass = 0; pass < 2; pass++) {
        const int qt = pass ? (NQT - 1 - pairIdx) : pairIdx;
        const int qbase = qt * 64;
        const int qlo = qbase + w * 16;

        // --- stage Q (fp16) into the Ks region, cache A-fragments ---
        uint32_t* Qstage = &Ks[0][0];
        for (int i = tid; i < 512; i += 128) {
            const int row = i >> 3;
            const int q = i & 7;
            uint4 v = *(const uint4*)&g_qkvh[(size_t)(bb * T_ + qbase + row) * C3_ + hh * D_ + q * 8];
            *(uint4*)&Qstage[row * KSU + q * 4] = v;
        }
        __syncthreads();

        uint32_t qa[4][4];
        #pragma unroll
        for (int kf = 0; kf < 4; kf++) {
            const int row = w * 16 + r;
            qa[kf][0] = Qstage[row * KSU + kf * 8 + c];
            qa[kf][1] = Qstage[(row + 8) * KSU + kf * 8 + c];
            qa[kf][2] = Qstage[row * KSU + kf * 8 + c + 4];
            qa[kf][3] = Qstage[(row + 8) * KSU + kf * 8 + c + 4];
        }
        __syncthreads();   // Q reads done before cp.async overwrites Ks

        const int nkt = qt + 1;

        // --- prologue: tile 0 -> buf 0 (64 keys) ---
        {
            for (int i = tid; i < 512; i += 128) {
                const int row = i >> 3;
                const int q = i & 7;
                cp_async16(ksb + (uint32_t)((row * KSU + q * 4) * 4),
                           kgbase + (size_t)row * C3_ + q * 8);
            }
            for (int i = tid; i < 512; i += 128) {
                const int d = i >> 3;
                const int q = i & 7;
                cp_async16(vsb + (uint32_t)((d * VSU + q * 4) * 4),
                           vgbase + (size_t)d * T_ + q * 8);
            }
            if (tid < 64) Ams[0][tid] = amask[bb * T_ + tid];
            CP_COMMIT();
        }

        float o[8][4];
        #pragma unroll
        for (int nb = 0; nb < 8; nb++)
            #pragma unroll
            for (int j = 0; j < 4; j++) o[nb][j] = 0.f;
        float mrow[2] = { -INFINITY, -INFINITY };
        float lrow[2] = { 0.f, 0.f };

        for (int kt = 0; kt < nkt; kt++) {
            const int buf = kt & 1;
            const int kbase = kt * 64;
            const bool more = (kt + 1) < nkt;

            if (more) {
                const int nb2 = buf ^ 1;
                const __half* kg = kgbase + (size_t)(kbase + 64) * C3_;
                const __half* vg = vgbase + kbase + 64;
                const uint32_t kdst = ksb + (uint32_t)(nb2 * 64 * KSU * 4);
                const uint32_t vdst = vsb + (uint32_t)(nb2 * 64 * VSU * 4);
                for (int i = tid; i < 512; i += 128) {
                    const int row = i >> 3;
                    const int q = i & 7;
                    cp_async16(kdst + (uint32_t)((row * KSU + q * 4) * 4),
                               kg + (size_t)row * C3_ + q * 8);
                }
                for (int i = tid; i < 512; i += 128) {
                    const int d = i >> 3;
                    const int q = i & 7;
                    cp_async16(vdst + (uint32_t)((d * VSU + q * 4) * 4),
                               vg + (size_t)d * T_ + q * 8);
                }
                if (tid < 64) Ams[nb2][tid] = amask[bb * T_ + kbase + 64 + tid];
                CP_COMMIT();
                CP_WAIT(1);
            } else {
                CP_WAIT(0);
            }
            __syncthreads();

            const uint32_t* ksB = &Ks[buf][0];
            const uint32_t* vsB = &Vs[buf][0];

            // --- S = Q K^T ---
            float s[8][4];
            #pragma unroll
            for (int nb = 0; nb < 8; nb++)
                #pragma unroll
                for (int j = 0; j < 4; j++) s[nb][j] = 0.f;
            #pragma unroll
            for (int kf = 0; kf < 4; kf++) {
                #pragma unroll
                for (int nb = 0; nb < 8; nb++) {
                    uint32_t bf[2];
                    bf[0] = ksB[(nb * 8 + r) * KSU + kf * 8 + c];
                    bf[1] = ksB[(nb * 8 + r) * KSU + kf * 8 + c + 4];
                    mma_f16(s[nb], qa[kf], bf);
                }
            }

            // --- scale + masks (causal mask only on diagonal tile) ---
            const bool needmask = (kt == nkt - 1);
            #pragma unroll
            for (int nb = 0; nb < 8; nb++) {
                const float a0 = Ams[buf][nb * 8 + 2 * c];
                const float a1 = Ams[buf][nb * 8 + 2 * c + 1];
                s[nb][0] = s[nb][0] * 0.125f + a0;
                s[nb][1] = s[nb][1] * 0.125f + a1;
                s[nb][2] = s[nb][2] * 0.125f + a0;
                s[nb][3] = s[nb][3] * 0.125f + a1;
                if (needmask) {
                    const int kc0 = kbase + nb * 8 + 2 * c;
                    const int q0 = qlo + r;
                    if (kc0 > q0)         s[nb][0] = -INFINITY;
                    if (kc0 + 1 > q0)     s[nb][1] = -INFINITY;
                    if (kc0 > q0 + 8)     s[nb][2] = -INFINITY;
                    if (kc0 + 1 > q0 + 8) s[nb][3] = -INFINITY;
                }
            }

            __syncwarp();

            // --- online softmax ---
            #pragma unroll
            for (int hf = 0; hf < 2; hf++) {
                float mx = -INFINITY;
                #pragma unroll
                for (int nb = 0; nb < 8; nb++)
                    mx = fmaxf(mx, fmaxf(s[nb][2 * hf], s[nb][2 * hf + 1]));
                mx = fmaxf(mx, __shfl_xor_sync(0xffffffffu, mx, 1));
                mx = fmaxf(mx, __shfl_xor_sync(0xffffffffu, mx, 2));
                const float mnew = fmaxf(mrow[hf], mx);
                const float corr = __expf(mrow[hf] - mnew);
                float sum = 0.f;
                const int prow = w * 16 + r + 8 * hf;
                #pragma unroll
                for (int nb = 0; nb < 8; nb++) {
                    const float p0 = __expf(s[nb][2 * hf] - mnew);
                    const float p1 = __expf(s[nb][2 * hf + 1] - mnew);
                    sum += p0 + p1;
                    Ps[prow * PSU + nb * 4 + c] = pack_h2(p0, p1);
                }
                sum += __shfl_xor_sync(0xffffffffu, sum, 1);
                sum += __shfl_xor_sync(0xffffffffu, sum, 2);
                lrow[hf] = lrow[hf] * corr + sum;
                mrow[hf] = mnew;
                #pragma unroll
                for (int nb = 0; nb < 8; nb++) {
                    o[nb][2 * hf]     *= corr;
                    o[nb][2 * hf + 1] *= corr;
                }
            }
            __syncwarp();

            // --- O += P V ---
            #pragma unroll
            for (int kf = 0; kf < 4; kf++) {
                uint32_t pa[4];
                const int prow = w * 16 + r;
                pa[0] = Ps[prow * PSU + kf * 8 + c];
                pa[1] = Ps[(prow + 8) * PSU + kf * 8 + c];
                pa[2] = Ps[prow * PSU + kf * 8 + c + 4];
                pa[3] = Ps[(prow + 8) * PSU + kf * 8 + c + 4];
                #pragma unroll
                for (int nb = 0; nb < 8; nb++) {
                    uint32_t bf[2];
                    bf[0] = vsB[(nb * 8 + r) * VSU + kf * 8 + c];
                    bf[1] = vsB[(nb * 8 + r) * VSU + kf * 8 + c + 4];
                    mma_f16(o[nb], pa, bf);
                }
            }
            __syncthreads();
        }

        // --- epilogue: write fp16 g_yh (proj GEMM input) ---
        const float inv0 = 1.f / lrow[0];
        const float inv1 = 1.f / lrow[1];
        const int row0 = bb * T_ + qbase + w * 16 + r;
        #pragma unroll
        for (int nb = 0; nb < 8; nb++) {
            const int col = hh * D_ + nb * 8 + 2 * c;
            __half2 v0 = __floats2half2_rn(o[nb][0] * inv0, o[nb][1] * inv0);
            __half2 v1 = __floats2half2_rn(o[nb][2] * inv1, o[nb][3] * inv1);
            *(__half2*)&g_yh[(size_t)row0 * C_ + col] = v0;
            *(__half2*)&g_yh[(size_t)(row0 + 8) * C_ + col] = v1;
        }
        __syncthreads();   // all buffers free before next pass stages Q
    }
}

// ----------------------------------------------------------------------------
// Launch.  Inputs: 0 x, 1 attention_mask, 2 attention_bias, 3 W_attn,
//                  4 b_attn, 5 W_proj, 6 b_proj
// ----------------------------------------------------------------------------
extern "C" void kernel_launch(void* const* d_in, const int* in_sizes, int n_in,
                              void* d_out, int out_size)
{
    (void)in_sizes; (void)n_in; (void)out_size;
    const float* x      = (const float*)d_in[0];
    const float* amask  = (const float*)d_in[1];
    const float* W_attn = (const float*)d_in[3];
    const float* b_attn = (const float*)d_in[4];
    const float* W_proj = (const float*)d_in[5];
    const float* b_proj = (const float*)d_in[6];
    float* out = (float*)d_out;

    __half *yh = nullptr, *xh = nullptr, *wt1 = nullptr, *wt2 = nullptr;
    cudaGetSymbolAddress((void**)&yh, g_yh);
    cudaGetSymbolAddress((void**)&xh, g_xh);
    cudaGetSymbolAddress((void**)&wt1, g_WT1h);
    cudaGetSymbolAddress((void**)&wt2, g_WT2h);

    // 0) Pre-convert operands to fp16
    round_fp16_kernel<<<(BT_ * C_) / (256 * 4), 256>>>(x, xh);
    transpose_fp16_kernel<<<dim3(C3_ / 32, C_ / 32), dim3(32, 8)>>>(W_attn, wt1, C_, C3_);
    transpose_fp16_kernel<<<dim3(C_ / 32, C_ / 32), dim3(32, 8)>>>(W_proj, wt2, C_, C_);

    // 1) QKV projection: Q/K -> g_qkvh fp16, V -> g_vt transposed fp16
    gemm_f16_kernel<<<dim3(C3_ / 128, BT_ / 128), 128>>>(
        xh, wt1, b_attn, out /*unused*/, BT_, C3_, C_, 1);

    // 2) Causal flash attention (paired q-tiles, perfectly balanced single wave)
    attn_f16_kernel<<<dim3(T_ / 128, H_, B_), 128>>>(amask);

    // 3) Output projection (fp16 in, fp32 out)
    gemm_f16_kernel<<<dim3(C_ / 128, BT_ / 128), 128>>>(
        yh, wt2, b_proj, out, BT_, C_, C_, 0);
}